// round 3
// baseline (speedup 1.0000x reference)
#include <cuda_runtime.h>
#include <cstdint>

// Problem constants
#define BB 4
#define TT 2048
#define DD 1024
#define HH 16
#define HD 64
#define DFF 4096
#define NROWS (BB * TT)          // 8192
#define EPS 1e-5f

// ---------------------------------------------------------------------------
// Single scratch arena (device global; allocation-free). Offsets in floats.
//   h   : LN output               [NROWS*DD]
//   q/k/v: projections            [NROWS*DD] each
//   ctx : attention output        [NROWS*DD]
//   x2  : post-attention residual [NROWS*DD]
//   ff  : FFN hidden              [NROWS*DFF]
// ---------------------------------------------------------------------------
#define SEG ((size_t)NROWS * DD)             // 8,388,608 floats
#define OFF_H   ((size_t)0)
#define OFF_Q   (SEG * 1)
#define OFF_K   (SEG * 2)
#define OFF_V   (SEG * 3)
#define OFF_CTX (SEG * 4)
#define OFF_X2  (SEG * 5)
#define OFF_FF  (SEG * 6)
#define SCRATCH_FLOATS (SEG * 6 + (size_t)NROWS * DFF)   // 83,886,080

__device__ float g_scratch[SCRATCH_FLOATS];

__device__ __forceinline__ const float* rsrc(const float* p, size_t off) {
    return p ? p : (const float*)(g_scratch + off);
}
__device__ __forceinline__ float* rdst(float* p, size_t off) {
    return p ? p : (g_scratch + off);
}

// ---------------------------------------------------------------------------
// LayerNorm: one block per row, 256 threads, D=1024 (1 float4 per thread)
// in: ext ptr or scratch offset; out: scratch offset
// ---------------------------------------------------------------------------
__global__ void __launch_bounds__(256) ln_kernel(
    const float* __restrict__ xext, size_t xoff,
    const float* __restrict__ g, const float* __restrict__ be, size_t ooff)
{
    const float* x = rsrc(xext, xoff);
    float* out = g_scratch + ooff;

    const int row = blockIdx.x;
    const int t   = threadIdx.x;
    const float4* xr = (const float4*)(x + (size_t)row * DD);
    float4 v = xr[t];

    float s = v.x + v.y + v.z + v.w;
    float q = v.x*v.x + v.y*v.y + v.z*v.z + v.w*v.w;
    #pragma unroll
    for (int o = 16; o; o >>= 1) {
        s += __shfl_xor_sync(0xffffffffu, s, o);
        q += __shfl_xor_sync(0xffffffffu, q, o);
    }
    __shared__ float ss[8], sq[8];
    if ((t & 31) == 0) { ss[t >> 5] = s; sq[t >> 5] = q; }
    __syncthreads();
    s = 0.f; q = 0.f;
    #pragma unroll
    for (int i = 0; i < 8; i++) { s += ss[i]; q += sq[i]; }

    const float mean = s * (1.0f / DD);
    const float var  = q * (1.0f / DD) - mean * mean;
    const float r    = rsqrtf(var + EPS);

    float4 gv = ((const float4*)g)[t];
    float4 bv = ((const float4*)be)[t];
    float4 o4;
    o4.x = (v.x - mean) * r * gv.x + bv.x;
    o4.y = (v.y - mean) * r * gv.y + bv.y;
    o4.z = (v.z - mean) * r * gv.z + bv.z;
    o4.w = (v.w - mean) * r * gv.w + bv.w;
    ((float4*)(out + (size_t)row * DD))[t] = o4;
}

// ---------------------------------------------------------------------------
// Tiled SGEMM: C[M,N] = A[M,K] @ B[K,N] (+bias, +resid, relu)
// 128x128 tile, BK=8, 256 threads, 8x8 per thread.
// A: scratch (offset). B/bias: ext ptrs. resid: ext or scratch.
// C: ext ptr (final output) or scratch.
// BMODE==1: B is head-blocked [H, K, 64]: B[k][c] = W[((c>>6)*K + k)*64 + (c&63)].
// ---------------------------------------------------------------------------
template<int BMODE, bool BIAS, bool RELU, bool RESID>
__global__ void __launch_bounds__(256) sgemm_kernel(
    size_t aoff, const float* __restrict__ B,
    const float* __restrict__ bias,
    const float* __restrict__ resid_ext, size_t resid_off,
    float* __restrict__ Cext, size_t coff,
    int M, int N, int K)
{
    const float* A = g_scratch + aoff;
    float* C = rdst(Cext, coff);
    const float* R = RESID ? rsrc(resid_ext, resid_off) : (const float*)nullptr;

    __shared__ float As[8][128];
    __shared__ float Bs[8][128];

    const int tid = threadIdx.x;
    const int m0 = blockIdx.y * 128;
    const int n0 = blockIdx.x * 128;

    const int arow = tid >> 1;          // 0..127
    const int acol = (tid & 1) << 2;    // 0 or 4
    const int brow = tid >> 5;          // 0..7
    const int bcol = (tid & 31) << 2;   // 0..124 step 4

    const float* Aptr = A + (size_t)(m0 + arow) * K + acol;
    const float* Bptr;
    long long bstep;
    if (BMODE == 1) {
        const int gcol = n0 + bcol;
        const int head = gcol >> 6;
        const int e    = gcol & 63;
        Bptr  = B + ((size_t)head * K + brow) * 64 + e;
        bstep = 8 * 64;
    } else {
        Bptr  = B + (size_t)brow * N + n0 + bcol;
        bstep = (long long)8 * N;
    }

    const int ty = (tid >> 4) << 3;
    const int tx = (tid & 15) << 3;

    float acc[8][8];
    #pragma unroll
    for (int i = 0; i < 8; i++)
        #pragma unroll
        for (int j = 0; j < 8; j++) acc[i][j] = 0.f;

    const int nk = K >> 3;
    for (int kk = 0; kk < nk; kk++) {
        const float4 av = *(const float4*)Aptr;
        const float4 bv = *(const float4*)Bptr;
        Aptr += 8;
        Bptr += bstep;

        __syncthreads();
        As[acol + 0][arow] = av.x;
        As[acol + 1][arow] = av.y;
        As[acol + 2][arow] = av.z;
        As[acol + 3][arow] = av.w;
        *(float4*)&Bs[brow][bcol] = bv;
        __syncthreads();

        #pragma unroll
        for (int k = 0; k < 8; k++) {
            const float4 a0 = *(const float4*)&As[k][ty];
            const float4 a1 = *(const float4*)&As[k][ty + 4];
            const float4 b0 = *(const float4*)&Bs[k][tx];
            const float4 b1 = *(const float4*)&Bs[k][tx + 4];
            const float ar[8] = {a0.x,a0.y,a0.z,a0.w,a1.x,a1.y,a1.z,a1.w};
            const float br[8] = {b0.x,b0.y,b0.z,b0.w,b1.x,b1.y,b1.z,b1.w};
            #pragma unroll
            for (int i = 0; i < 8; i++)
                #pragma unroll
                for (int j = 0; j < 8; j++)
                    acc[i][j] += ar[i] * br[j];
        }
    }

    float bvreg[8];
    if (BIAS) {
        #pragma unroll
        for (int j = 0; j < 8; j++) bvreg[j] = bias[n0 + tx + j];
    }
    #pragma unroll
    for (int i = 0; i < 8; i++) {
        const int gr = m0 + ty + i;
        float* Crow = C + (size_t)gr * N + n0 + tx;
        const float* Rrow = RESID ? (R + (size_t)gr * N + n0 + tx) : (const float*)nullptr;
        #pragma unroll
        for (int j = 0; j < 8; j += 4) {
            float vv0 = acc[i][j + 0];
            float vv1 = acc[i][j + 1];
            float vv2 = acc[i][j + 2];
            float vv3 = acc[i][j + 3];
            if (BIAS)  { vv0 += bvreg[j+0]; vv1 += bvreg[j+1]; vv2 += bvreg[j+2]; vv3 += bvreg[j+3]; }
            if (RESID) { vv0 += Rrow[j+0];  vv1 += Rrow[j+1];  vv2 += Rrow[j+2];  vv3 += Rrow[j+3]; }
            if (RELU)  { vv0 = fmaxf(vv0, 0.f); vv1 = fmaxf(vv1, 0.f); vv2 = fmaxf(vv2, 0.f); vv3 = fmaxf(vv3, 0.f); }
            float4 o; o.x = vv0; o.y = vv1; o.z = vv2; o.w = vv3;
            *(float4*)(Crow + j) = o;
        }
    }
}

// ---------------------------------------------------------------------------
// Causal flash attention, fp32.
// Grid: (T/64, H, B). Block: 64 threads, one query row per thread.
// Scores staged in SMEM (Ss) to keep registers under control.
// q/k/v/ctx live in scratch, layout [B*T, D] with column = head*64 + e.
// ---------------------------------------------------------------------------
__global__ void __launch_bounds__(64) attn_kernel()
{
    __shared__ float Ks[64][64];
    __shared__ float Vs[64][64];
    __shared__ float Ss[64 * 64];     // Ss[j*64 + tid]

    const float* q = g_scratch + OFF_Q;
    const float* k = g_scratch + OFF_K;
    const float* v = g_scratch + OFF_V;
    float* ctx     = g_scratch + OFF_CTX;

    const int qt   = blockIdx.x;
    const int head = blockIdx.y;
    const int b    = blockIdx.z;
    const int tid  = threadIdx.x;
    const int qi   = qt * 64 + tid;

    const size_t qoff = ((size_t)b * TT + qi) * DD + head * 64;

    float Q[64];
    #pragma unroll
    for (int e = 0; e < 64; e += 4) {
        const float4 t4 = *(const float4*)(q + qoff + e);
        Q[e+0] = t4.x; Q[e+1] = t4.y; Q[e+2] = t4.z; Q[e+3] = t4.w;
    }

    float acc[64];
    #pragma unroll
    for (int e = 0; e < 64; e++) acc[e] = 0.f;
    float m = -1e30f, l = 0.f;

    const int ktiles = qt + 1;
    for (int kt = 0; kt < ktiles; kt++) {
        __syncthreads();
        const size_t base = ((size_t)b * TT + (size_t)kt * 64) * DD + head * 64;
        #pragma unroll
        for (int it = 0; it < 16; it++) {
            const int idx = tid + it * 64;       // float4 units
            const int j  = idx >> 4;
            const int e4 = (idx & 15) << 2;
            *(float4*)&Ks[j][e4] = *(const float4*)(k + base + (size_t)j * DD + e4);
            *(float4*)&Vs[j][e4] = *(const float4*)(v + base + (size_t)j * DD + e4);
        }
        __syncthreads();

        float mt = m;
        const bool diag = (kt == qt);
        #pragma unroll 4
        for (int j = 0; j < 64; j++) {
            float a = 0.f;
            #pragma unroll
            for (int e = 0; e < 64; e++) a += Q[e] * Ks[j][e];
            float sv = a * 0.125f;               // 1/sqrt(64)
            if (diag && (j > tid)) sv = -1e30f;
            Ss[j * 64 + tid] = sv;
            mt = fmaxf(mt, sv);
        }

        const float corr = __expf(m - mt);
        l *= corr;
        #pragma unroll
        for (int e = 0; e < 64; e++) acc[e] *= corr;

        #pragma unroll 2
        for (int j = 0; j < 64; j++) {
            const float p = __expf(Ss[j * 64 + tid] - mt);
            l += p;
            #pragma unroll
            for (int e = 0; e < 64; e++) acc[e] += p * Vs[j][e];
        }
        m = mt;
    }

    const float inv = 1.f / l;
    float* co = ctx + qoff;
    #pragma unroll
    for (int e = 0; e < 64; e += 4) {
        float4 o;
        o.x = acc[e+0] * inv; o.y = acc[e+1] * inv;
        o.z = acc[e+2] * inv; o.w = acc[e+3] * inv;
        *(float4*)(co + e) = o;
    }
}

// ---------------------------------------------------------------------------
// Launch — kernel launches only (graph-capture safe, no runtime API calls)
// ---------------------------------------------------------------------------
extern "C" void kernel_launch(void* const* d_in, const int* in_sizes, int n_in,
                              void* d_out, int out_size)
{
    const float* x   = (const float*)d_in[0];
    const float* Wq  = (const float*)d_in[1];
    const float* Wk  = (const float*)d_in[2];
    const float* Wv  = (const float*)d_in[3];
    const float* Wo  = (const float*)d_in[4];
    const float* bo  = (const float*)d_in[5];
    const float* W1  = (const float*)d_in[6];
    const float* b1  = (const float*)d_in[7];
    const float* W2  = (const float*)d_in[8];
    const float* b2  = (const float*)d_in[9];
    const float* g1  = (const float*)d_in[10];
    const float* be1 = (const float*)d_in[11];
    const float* g2  = (const float*)d_in[12];
    const float* be2 = (const float*)d_in[13];
    float* out = (float*)d_out;

    // 1) LN1: x -> h
    ln_kernel<<<NROWS, 256>>>(x, 0, g1, be1, OFF_H);

    // 2) QKV projections (head-blocked weight layout): h -> q/k/v
    dim3 gq(DD / 128, NROWS / 128);
    sgemm_kernel<1, false, false, false><<<gq, 256>>>(OFF_H, Wq, nullptr, nullptr, 0, nullptr, OFF_Q, NROWS, DD, DD);
    sgemm_kernel<1, false, false, false><<<gq, 256>>>(OFF_H, Wk, nullptr, nullptr, 0, nullptr, OFF_K, NROWS, DD, DD);
    sgemm_kernel<1, false, false, false><<<gq, 256>>>(OFF_H, Wv, nullptr, nullptr, 0, nullptr, OFF_V, NROWS, DD, DD);

    // 3) Causal flash attention: q,k,v -> ctx
    attn_kernel<<<dim3(TT / 64, HH, BB), 64>>>();

    // 4) Output projection + bias + residual(x): ctx -> x2
    sgemm_kernel<0, true, false, true><<<gq, 256>>>(OFF_CTX, Wo, bo, x, 0, nullptr, OFF_X2, NROWS, DD, DD);

    // 5) LN2: x2 -> h
    ln_kernel<<<NROWS, 256>>>(nullptr, OFF_X2, g2, be2, OFF_H);

    // 6) FFN1 (+bias, relu): h -> ff
    dim3 gf1(DFF / 128, NROWS / 128);
    sgemm_kernel<0, true, true, false><<<gf1, 256>>>(OFF_H, W1, b1, nullptr, 0, nullptr, OFF_FF, NROWS, DFF, DD);

    // 7) FFN2 (+bias, +residual x2) -> final output
    sgemm_kernel<0, true, false, true><<<gq, 256>>>(OFF_FF, W2, b2, nullptr, OFF_X2, out, 0, NROWS, DD, DFF);
}

// round 4
// speedup vs baseline: 2.0326x; 2.0326x over previous
#include <cuda_runtime.h>
#include <cstdint>

// Problem constants
#define BB 4
#define TT 2048
#define DD 1024
#define HH 16
#define HD 64
#define DFF 4096
#define NROWS (BB * TT)          // 8192
#define EPS 1e-5f

// ---------------------------------------------------------------------------
// Scratch arena
// ---------------------------------------------------------------------------
#define SEG ((size_t)NROWS * DD)
#define OFF_H   ((size_t)0)
#define OFF_Q   (SEG * 1)
#define OFF_K   (SEG * 2)
#define OFF_V   (SEG * 3)
#define OFF_CTX (SEG * 4)
#define OFF_X2  (SEG * 5)
#define OFF_FF  (SEG * 6)
#define SCRATCH_FLOATS (SEG * 6 + (size_t)NROWS * DFF)

__device__ float g_scratch[SCRATCH_FLOATS];

__device__ __forceinline__ const float* rsrc(const float* p, size_t off) {
    return p ? p : (const float*)(g_scratch + off);
}
__device__ __forceinline__ float* rdst(float* p, size_t off) {
    return p ? p : (g_scratch + off);
}

__device__ __forceinline__ unsigned f2tf(float f) {
    unsigned u;
    asm("cvt.rna.tf32.f32 %0, %1;" : "=r"(u) : "f"(f));
    return u;
}

// ---------------------------------------------------------------------------
// LayerNorm (unchanged)
// ---------------------------------------------------------------------------
__global__ void __launch_bounds__(256) ln_kernel(
    const float* __restrict__ xext, size_t xoff,
    const float* __restrict__ g, const float* __restrict__ be, size_t ooff)
{
    const float* x = rsrc(xext, xoff);
    float* out = g_scratch + ooff;

    const int row = blockIdx.x;
    const int t   = threadIdx.x;
    const float4* xr = (const float4*)(x + (size_t)row * DD);
    float4 v = xr[t];

    float s = v.x + v.y + v.z + v.w;
    float q = v.x*v.x + v.y*v.y + v.z*v.z + v.w*v.w;
    #pragma unroll
    for (int o = 16; o; o >>= 1) {
        s += __shfl_xor_sync(0xffffffffu, s, o);
        q += __shfl_xor_sync(0xffffffffu, q, o);
    }
    __shared__ float ss[8], sq[8];
    if ((t & 31) == 0) { ss[t >> 5] = s; sq[t >> 5] = q; }
    __syncthreads();
    s = 0.f; q = 0.f;
    #pragma unroll
    for (int i = 0; i < 8; i++) { s += ss[i]; q += sq[i]; }

    const float mean = s * (1.0f / DD);
    const float var  = q * (1.0f / DD) - mean * mean;
    const float r    = rsqrtf(var + EPS);

    float4 gv = ((const float4*)g)[t];
    float4 bv = ((const float4*)be)[t];
    float4 o4;
    o4.x = (v.x - mean) * r * gv.x + bv.x;
    o4.y = (v.y - mean) * r * gv.y + bv.y;
    o4.z = (v.z - mean) * r * gv.z + bv.z;
    o4.w = (v.w - mean) * r * gv.w + bv.w;
    ((float4*)(out + (size_t)row * DD))[t] = o4;
}

// ---------------------------------------------------------------------------
// TF32 tensor-core GEMM: C[M,N] = A[M,K] @ B[K,N] (+bias, +resid, relu)
// 128x128x16 tiles, 256 threads = 8 warps (2x4), 64x32 per warp,
// mma.sync.m16n8k8.tf32, cp.async double buffering.
// BMODE==1: B is head-blocked [H, K, 64]: B[k][c] = W[((c>>6)*K + k)*64 + (c&63)].
// ---------------------------------------------------------------------------
template<int BMODE, bool BIAS, bool RELU, bool RESID>
__global__ void __launch_bounds__(256) tgemm_kernel(
    size_t aoff, const float* __restrict__ B,
    const float* __restrict__ bias,
    const float* __restrict__ resid_ext, size_t resid_off,
    float* __restrict__ Cext, size_t coff,
    int M, int N, int K)
{
    const float* A = g_scratch + aoff;
    float* C = rdst(Cext, coff);
    const float* R = RESID ? rsrc(resid_ext, resid_off) : (const float*)nullptr;

    // A stored [m][k] stride 20 (conflict-free for frag reads, 16B-aligned rows)
    // B stored [k][n] stride 136 (conflict-free, 16B-aligned rows)
    __shared__ float As[2][128][20];
    __shared__ float Bs[2][16][136];

    const int tid  = threadIdx.x;
    const int wid  = tid >> 5;
    const int lane = tid & 31;
    const int m0 = blockIdx.y * 128;
    const int n0 = blockIdx.x * 128;
    const int warp_m = (wid >> 2) * 64;    // 0 or 64
    const int warp_n = (wid & 3) * 32;     // 0,32,64,96
    const int g = lane >> 2;               // 0..7
    const int t = lane & 3;                // 0..3

    float acc[4][4][4];
    #pragma unroll
    for (int mt = 0; mt < 4; mt++)
        #pragma unroll
        for (int nt = 0; nt < 4; nt++)
            #pragma unroll
            for (int r = 0; r < 4; r++) acc[mt][nt][r] = 0.f;

    const int nk = K >> 4;   // K/16

    auto issue = [&](int kk, int buf) {
        // A tile: 128 rows x 16 cols = 512 float4
        #pragma unroll
        for (int i = 0; i < 2; i++) {
            const int chunk = tid + i * 256;
            const int row = chunk >> 2;
            const int kc  = (chunk & 3) << 2;
            const float* gp = A + (size_t)(m0 + row) * K + kk * 16 + kc;
            unsigned sp = (unsigned)__cvta_generic_to_shared(&As[buf][row][kc]);
            asm volatile("cp.async.cg.shared.global [%0], [%1], 16;\n" :: "r"(sp), "l"(gp));
        }
        // B tile: 16 rows x 128 cols = 512 float4
        #pragma unroll
        for (int i = 0; i < 2; i++) {
            const int chunk = tid + i * 256;
            const int kr = chunk >> 5;
            const int nc = (chunk & 31) << 2;
            const float* gp;
            if (BMODE == 1) {
                const int gcol = n0 + nc;
                const int head = gcol >> 6;
                const int e    = gcol & 63;
                gp = B + ((size_t)head * K + kk * 16 + kr) * 64 + e;
            } else {
                gp = B + (size_t)(kk * 16 + kr) * N + n0 + nc;
            }
            unsigned sp = (unsigned)__cvta_generic_to_shared(&Bs[buf][kr][nc]);
            asm volatile("cp.async.cg.shared.global [%0], [%1], 16;\n" :: "r"(sp), "l"(gp));
        }
        asm volatile("cp.async.commit_group;\n");
    };

    issue(0, 0);

    for (int kk = 0; kk < nk; kk++) {
        const int buf = kk & 1;
        if (kk + 1 < nk) {
            issue(kk + 1, buf ^ 1);
            asm volatile("cp.async.wait_group 1;\n");
        } else {
            asm volatile("cp.async.wait_group 0;\n");
        }
        __syncthreads();

        #pragma unroll
        for (int ks = 0; ks < 16; ks += 8) {
            unsigned af[4][4], bf[4][2];
            #pragma unroll
            for (int mt = 0; mt < 4; mt++) {
                const int r = warp_m + mt * 16;
                af[mt][0] = f2tf(As[buf][r + g    ][ks + t    ]);
                af[mt][1] = f2tf(As[buf][r + g + 8][ks + t    ]);
                af[mt][2] = f2tf(As[buf][r + g    ][ks + t + 4]);
                af[mt][3] = f2tf(As[buf][r + g + 8][ks + t + 4]);
            }
            #pragma unroll
            for (int nt = 0; nt < 4; nt++) {
                const int c = warp_n + nt * 8;
                bf[nt][0] = f2tf(Bs[buf][ks + t    ][c + g]);
                bf[nt][1] = f2tf(Bs[buf][ks + t + 4][c + g]);
            }
            #pragma unroll
            for (int mt = 0; mt < 4; mt++)
                #pragma unroll
                for (int nt = 0; nt < 4; nt++) {
                    asm volatile(
                        "mma.sync.aligned.m16n8k8.row.col.f32.tf32.tf32.f32 "
                        "{%0,%1,%2,%3}, {%4,%5,%6,%7}, {%8,%9}, {%0,%1,%2,%3};\n"
                        : "+f"(acc[mt][nt][0]), "+f"(acc[mt][nt][1]),
                          "+f"(acc[mt][nt][2]), "+f"(acc[mt][nt][3])
                        : "r"(af[mt][0]), "r"(af[mt][1]), "r"(af[mt][2]), "r"(af[mt][3]),
                          "r"(bf[nt][0]), "r"(bf[nt][1]));
                }
        }
        __syncthreads();
    }

    // Epilogue: c0 @(g, 2t), c1 @(g, 2t+1), c2 @(g+8, 2t), c3 @(g+8, 2t+1)
    #pragma unroll
    for (int mt = 0; mt < 4; mt++) {
        #pragma unroll
        for (int half = 0; half < 2; half++) {
            const int gr = m0 + warp_m + mt * 16 + g + half * 8;
            float* Crow = C + (size_t)gr * N;
            const float* Rrow = RESID ? (R + (size_t)gr * N) : (const float*)nullptr;
            #pragma unroll
            for (int nt = 0; nt < 4; nt++) {
                const int gc = n0 + warp_n + nt * 8 + 2 * t;
                float v0 = acc[mt][nt][half * 2 + 0];
                float v1 = acc[mt][nt][half * 2 + 1];
                if (BIAS)  { v0 += bias[gc]; v1 += bias[gc + 1]; }
                if (RESID) { v0 += Rrow[gc]; v1 += Rrow[gc + 1]; }
                if (RELU)  { v0 = fmaxf(v0, 0.f); v1 = fmaxf(v1, 0.f); }
                *(float2*)(Crow + gc) = make_float2(v0, v1);
            }
        }
    }
}

// ---------------------------------------------------------------------------
// Causal flash attention (unchanged from R3)
// ---------------------------------------------------------------------------
__global__ void __launch_bounds__(64) attn_kernel()
{
    __shared__ float Ks[64][64];
    __shared__ float Vs[64][64];
    __shared__ float Ss[64 * 64];

    const float* q = g_scratch + OFF_Q;
    const float* k = g_scratch + OFF_K;
    const float* v = g_scratch + OFF_V;
    float* ctx     = g_scratch + OFF_CTX;

    const int qt   = blockIdx.x;
    const int head = blockIdx.y;
    const int b    = blockIdx.z;
    const int tid  = threadIdx.x;
    const int qi   = qt * 64 + tid;

    const size_t qoff = ((size_t)b * TT + qi) * DD + head * 64;

    float Q[64];
    #pragma unroll
    for (int e = 0; e < 64; e += 4) {
        const float4 t4 = *(const float4*)(q + qoff + e);
        Q[e+0] = t4.x; Q[e+1] = t4.y; Q[e+2] = t4.z; Q[e+3] = t4.w;
    }

    float acc[64];
    #pragma unroll
    for (int e = 0; e < 64; e++) acc[e] = 0.f;
    float m = -1e30f, l = 0.f;

    const int ktiles = qt + 1;
    for (int kt = 0; kt < ktiles; kt++) {
        __syncthreads();
        const size_t base = ((size_t)b * TT + (size_t)kt * 64) * DD + head * 64;
        #pragma unroll
        for (int it = 0; it < 16; it++) {
            const int idx = tid + it * 64;
            const int j  = idx >> 4;
            const int e4 = (idx & 15) << 2;
            *(float4*)&Ks[j][e4] = *(const float4*)(k + base + (size_t)j * DD + e4);
            *(float4*)&Vs[j][e4] = *(const float4*)(v + base + (size_t)j * DD + e4);
        }
        __syncthreads();

        float mt = m;
        const bool diag = (kt == qt);
        #pragma unroll 4
        for (int j = 0; j < 64; j++) {
            float a = 0.f;
            #pragma unroll
            for (int e = 0; e < 64; e++) a += Q[e] * Ks[j][e];
            float sv = a * 0.125f;
            if (diag && (j > tid)) sv = -1e30f;
            Ss[j * 64 + tid] = sv;
            mt = fmaxf(mt, sv);
        }

        const float corr = __expf(m - mt);
        l *= corr;
        #pragma unroll
        for (int e = 0; e < 64; e++) acc[e] *= corr;

        #pragma unroll 2
        for (int j = 0; j < 64; j++) {
            const float p = __expf(Ss[j * 64 + tid] - mt);
            l += p;
            #pragma unroll
            for (int e = 0; e < 64; e++) acc[e] += p * Vs[j][e];
        }
        m = mt;
    }

    const float inv = 1.f / l;
    float* co = ctx + qoff;
    #pragma unroll
    for (int e = 0; e < 64; e += 4) {
        float4 o;
        o.x = acc[e+0] * inv; o.y = acc[e+1] * inv;
        o.z = acc[e+2] * inv; o.w = acc[e+3] * inv;
        *(float4*)(co + e) = o;
    }
}

// ---------------------------------------------------------------------------
// Launch
// ---------------------------------------------------------------------------
extern "C" void kernel_launch(void* const* d_in, const int* in_sizes, int n_in,
                              void* d_out, int out_size)
{
    const float* x   = (const float*)d_in[0];
    const float* Wq  = (const float*)d_in[1];
    const float* Wk  = (const float*)d_in[2];
    const float* Wv  = (const float*)d_in[3];
    const float* Wo  = (const float*)d_in[4];
    const float* bo  = (const float*)d_in[5];
    const float* W1  = (const float*)d_in[6];
    const float* b1  = (const float*)d_in[7];
    const float* W2  = (const float*)d_in[8];
    const float* b2  = (const float*)d_in[9];
    const float* g1  = (const float*)d_in[10];
    const float* be1 = (const float*)d_in[11];
    const float* g2  = (const float*)d_in[12];
    const float* be2 = (const float*)d_in[13];
    float* out = (float*)d_out;

    // 1) LN1: x -> h
    ln_kernel<<<NROWS, 256>>>(x, 0, g1, be1, OFF_H);

    // 2) QKV projections
    dim3 gq(DD / 128, NROWS / 128);
    tgemm_kernel<1, false, false, false><<<gq, 256>>>(OFF_H, Wq, nullptr, nullptr, 0, nullptr, OFF_Q, NROWS, DD, DD);
    tgemm_kernel<1, false, false, false><<<gq, 256>>>(OFF_H, Wk, nullptr, nullptr, 0, nullptr, OFF_K, NROWS, DD, DD);
    tgemm_kernel<1, false, false, false><<<gq, 256>>>(OFF_H, Wv, nullptr, nullptr, 0, nullptr, OFF_V, NROWS, DD, DD);

    // 3) Causal flash attention
    attn_kernel<<<dim3(TT / 64, HH, BB), 64>>>();

    // 4) Output projection + bias + residual(x): ctx -> x2
    tgemm_kernel<0, true, false, true><<<gq, 256>>>(OFF_CTX, Wo, bo, x, 0, nullptr, OFF_X2, NROWS, DD, DD);

    // 5) LN2: x2 -> h
    ln_kernel<<<NROWS, 256>>>(nullptr, OFF_X2, g2, be2, OFF_H);

    // 6) FFN1 (+bias, relu): h -> ff
    dim3 gf1(DFF / 128, NROWS / 128);
    tgemm_kernel<0, true, true, false><<<gf1, 256>>>(OFF_H, W1, b1, nullptr, 0, nullptr, OFF_FF, NROWS, DFF, DD);

    // 7) FFN2 (+bias, +residual x2) -> final output
    tgemm_kernel<0, true, false, true><<<gq, 256>>>(OFF_FF, W2, b2, nullptr, OFF_X2, out, 0, NROWS, DD, DFF);
}

// round 5
// speedup vs baseline: 3.2934x; 1.6203x over previous
#include <cuda_runtime.h>
#include <cstdint>

// Problem constants
#define BB 4
#define TT 2048
#define DD 1024
#define HH 16
#define HD 64
#define DFF 4096
#define NROWS (BB * TT)          // 8192
#define EPS 1e-5f

// ---------------------------------------------------------------------------
// Scratch arena (floats)
// ---------------------------------------------------------------------------
#define SEG ((size_t)NROWS * DD)             // 8,388,608
#define MW  ((size_t)1024 * 1024)
#define OFF_H   ((size_t)0)
#define OFF_Q   (SEG * 1)
#define OFF_K   (SEG * 2)
#define OFF_V   (SEG * 3)
#define OFF_CTX (SEG * 4)
#define OFF_X2  (SEG * 5)
#define OFF_FF  (SEG * 6)
#define OFF_WC  (SEG * 6 + (size_t)NROWS * DFF)
#define OFF_WQC (OFF_WC + MW * 0)
#define OFF_WKC (OFF_WC + MW * 1)
#define OFF_WVC (OFF_WC + MW * 2)
#define OFF_WOC (OFF_WC + MW * 3)
#define OFF_W1C (OFF_WC + MW * 4)
#define OFF_W2C (OFF_WC + MW * 8)
#define SCRATCH_FLOATS (OFF_WC + MW * 12)

__device__ __align__(256) float g_scratch[SCRATCH_FLOATS];

__device__ __forceinline__ const float* rsrc(const float* p, size_t off) {
    return p ? p : (const float*)(g_scratch + off);
}
__device__ __forceinline__ float* rdst(float* p, size_t off) {
    return p ? p : (g_scratch + off);
}

__device__ __forceinline__ unsigned f2tf(float f) {
    unsigned u;
    asm("cvt.rna.tf32.f32 %0, %1;" : "=r"(u) : "f"(f));
    return u;
}
__device__ __forceinline__ float tfr(float f) {   // round value to tf32-clean fp32
    return __uint_as_float(f2tf(f));
}

__device__ __forceinline__ void cpa16(void* s, const void* g) {
    unsigned sp = (unsigned)__cvta_generic_to_shared(s);
    asm volatile("cp.async.cg.shared.global [%0], [%1], 16;\n" :: "r"(sp), "l"(g));
}
__device__ __forceinline__ void cpa_commit() { asm volatile("cp.async.commit_group;\n"); }
__device__ __forceinline__ void cpa_wait0()  { asm volatile("cp.async.wait_group 0;\n"); }
__device__ __forceinline__ void cpa_wait1()  { asm volatile("cp.async.wait_group 1;\n"); }

__device__ __forceinline__ void mma_tf32(float* c, const unsigned* a, const unsigned* b) {
    asm volatile(
        "mma.sync.aligned.m16n8k8.row.col.f32.tf32.tf32.f32 "
        "{%0,%1,%2,%3}, {%4,%5,%6,%7}, {%8,%9}, {%0,%1,%2,%3};\n"
        : "+f"(c[0]), "+f"(c[1]), "+f"(c[2]), "+f"(c[3])
        : "r"(a[0]), "r"(a[1]), "r"(a[2]), "r"(a[3]), "r"(b[0]), "r"(b[1]));
}

// ---------------------------------------------------------------------------
// Weight conversion: round all weights to tf32-clean fp32 copies in scratch.
// 3,145,728 float4 total: Wq,Wk,Wv,Wo (256Ki f4 each), W1 (1Mi), W2 (1Mi).
// ---------------------------------------------------------------------------
__global__ void __launch_bounds__(256) wconv_kernel(
    const float4* __restrict__ wq, const float4* __restrict__ wk,
    const float4* __restrict__ wv, const float4* __restrict__ wo,
    const float4* __restrict__ w1, const float4* __restrict__ w2)
{
    const size_t Q4 = MW / 4;   // 262144
    const size_t i = (size_t)blockIdx.x * 256 + threadIdx.x;
    float4 v;
    if      (i < Q4)          v = wq[i];
    else if (i < Q4 * 2)      v = wk[i - Q4];
    else if (i < Q4 * 3)      v = wv[i - Q4 * 2];
    else if (i < Q4 * 4)      v = wo[i - Q4 * 3];
    else if (i < Q4 * 8)      v = w1[i - Q4 * 4];
    else                      v = w2[i - Q4 * 8];
    v.x = tfr(v.x); v.y = tfr(v.y); v.z = tfr(v.z); v.w = tfr(v.w);
    ((float4*)(g_scratch + OFF_WC))[i] = v;
}

// ---------------------------------------------------------------------------
// LayerNorm (rounds output to tf32-clean — it only feeds GEMM A operands)
// ---------------------------------------------------------------------------
__global__ void __launch_bounds__(256) ln_kernel(
    const float* __restrict__ xext, size_t xoff,
    const float* __restrict__ g, const float* __restrict__ be, size_t ooff)
{
    const float* x = rsrc(xext, xoff);
    float* out = g_scratch + ooff;

    const int row = blockIdx.x;
    const int t   = threadIdx.x;
    const float4* xr = (const float4*)(x + (size_t)row * DD);
    float4 v = xr[t];

    float s = v.x + v.y + v.z + v.w;
    float q = v.x*v.x + v.y*v.y + v.z*v.z + v.w*v.w;
    #pragma unroll
    for (int o = 16; o; o >>= 1) {
        s += __shfl_xor_sync(0xffffffffu, s, o);
        q += __shfl_xor_sync(0xffffffffu, q, o);
    }
    __shared__ float ss[8], sq[8];
    if ((t & 31) == 0) { ss[t >> 5] = s; sq[t >> 5] = q; }
    __syncthreads();
    s = 0.f; q = 0.f;
    #pragma unroll
    for (int i = 0; i < 8; i++) { s += ss[i]; q += sq[i]; }

    const float mean = s * (1.0f / DD);
    const float var  = q * (1.0f / DD) - mean * mean;
    const float r    = rsqrtf(var + EPS);

    float4 gv = ((const float4*)g)[t];
    float4 bv = ((const float4*)be)[t];
    float4 o4;
    o4.x = tfr((v.x - mean) * r * gv.x + bv.x);
    o4.y = tfr((v.y - mean) * r * gv.y + bv.y);
    o4.z = tfr((v.z - mean) * r * gv.z + bv.z);
    o4.w = tfr((v.w - mean) * r * gv.w + bv.w);
    ((float4*)(out + (size_t)row * DD))[t] = o4;
}

// ---------------------------------------------------------------------------
// TF32 tensor-core GEMM (operands pre-rounded; no cvt in mainloop).
// C[M,N] = A[M,K] @ B[K,N] (+bias, +resid, relu, round)
// A: scratch offset. B: scratch offset (converted weights). 128x128x16 tiles.
// BMODE==1: B head-blocked [H, K, 64].
// ---------------------------------------------------------------------------
template<int BMODE, bool BIAS, bool RELU, bool RESID, bool ROUND>
__global__ void __launch_bounds__(256) tgemm_kernel(
    size_t aoff, size_t boff,
    const float* __restrict__ bias,
    const float* __restrict__ resid_ext, size_t resid_off,
    float* __restrict__ Cext, size_t coff,
    int M, int N, int K)
{
    const float* A = g_scratch + aoff;
    const float* B = g_scratch + boff;
    float* C = rdst(Cext, coff);
    const float* R = RESID ? rsrc(resid_ext, resid_off) : (const float*)nullptr;

    __shared__ float As[2][128][20];
    __shared__ float Bs[2][16][136];

    const int tid  = threadIdx.x;
    const int wid  = tid >> 5;
    const int lane = tid & 31;
    const int m0 = blockIdx.y * 128;
    const int n0 = blockIdx.x * 128;
    const int warp_m = (wid >> 2) * 64;
    const int warp_n = (wid & 3) * 32;
    const int g = lane >> 2;
    const int t = lane & 3;

    float acc[4][4][4];
    #pragma unroll
    for (int mt = 0; mt < 4; mt++)
        #pragma unroll
        for (int nt = 0; nt < 4; nt++)
            #pragma unroll
            for (int r = 0; r < 4; r++) acc[mt][nt][r] = 0.f;

    const int nk = K >> 4;

    auto issue = [&](int kk, int buf) {
        #pragma unroll
        for (int i = 0; i < 2; i++) {
            const int chunk = tid + i * 256;
            const int row = chunk >> 2;
            const int kc  = (chunk & 3) << 2;
            cpa16(&As[buf][row][kc], A + (size_t)(m0 + row) * K + kk * 16 + kc);
        }
        #pragma unroll
        for (int i = 0; i < 2; i++) {
            const int chunk = tid + i * 256;
            const int kr = chunk >> 5;
            const int nc = (chunk & 31) << 2;
            const float* gp;
            if (BMODE == 1) {
                const int gcol = n0 + nc;
                gp = B + ((size_t)(gcol >> 6) * K + kk * 16 + kr) * 64 + (gcol & 63);
            } else {
                gp = B + (size_t)(kk * 16 + kr) * N + n0 + nc;
            }
            cpa16(&Bs[buf][kr][nc], gp);
        }
        cpa_commit();
    };

    issue(0, 0);

    for (int kk = 0; kk < nk; kk++) {
        const int buf = kk & 1;
        if (kk + 1 < nk) { issue(kk + 1, buf ^ 1); cpa_wait1(); }
        else             { cpa_wait0(); }
        __syncthreads();

        #pragma unroll
        for (int ks = 0; ks < 16; ks += 8) {
            unsigned af[4][4], bf[4][2];
            #pragma unroll
            for (int mt = 0; mt < 4; mt++) {
                const int r = warp_m + mt * 16;
                af[mt][0] = __float_as_uint(As[buf][r + g    ][ks + t    ]);
                af[mt][1] = __float_as_uint(As[buf][r + g + 8][ks + t    ]);
                af[mt][2] = __float_as_uint(As[buf][r + g    ][ks + t + 4]);
                af[mt][3] = __float_as_uint(As[buf][r + g + 8][ks + t + 4]);
            }
            #pragma unroll
            for (int nt = 0; nt < 4; nt++) {
                const int c = warp_n + nt * 8;
                bf[nt][0] = __float_as_uint(Bs[buf][ks + t    ][c + g]);
                bf[nt][1] = __float_as_uint(Bs[buf][ks + t + 4][c + g]);
            }
            #pragma unroll
            for (int mt = 0; mt < 4; mt++)
                #pragma unroll
                for (int nt = 0; nt < 4; nt++)
                    mma_tf32(acc[mt][nt], af[mt], bf[nt]);
        }
        __syncthreads();
    }

    #pragma unroll
    for (int mt = 0; mt < 4; mt++) {
        #pragma unroll
        for (int half = 0; half < 2; half++) {
            const int gr = m0 + warp_m + mt * 16 + g + half * 8;
            float* Crow = C + (size_t)gr * N;
            const float* Rrow = RESID ? (R + (size_t)gr * N) : (const float*)nullptr;
            #pragma unroll
            for (int nt = 0; nt < 4; nt++) {
                const int gc = n0 + warp_n + nt * 8 + 2 * t;
                float v0 = acc[mt][nt][half * 2 + 0];
                float v1 = acc[mt][nt][half * 2 + 1];
                if (BIAS)  { v0 += bias[gc]; v1 += bias[gc + 1]; }
                if (RESID) { v0 += Rrow[gc]; v1 += Rrow[gc + 1]; }
                if (RELU)  { v0 = fmaxf(v0, 0.f); v1 = fmaxf(v1, 0.f); }
                if (ROUND) { v0 = tfr(v0); v1 = tfr(v1); }
                *(float2*)(Crow + gc) = make_float2(v0, v1);
            }
        }
    }
}

// ---------------------------------------------------------------------------
// Tensor-core causal flash attention (tf32).
// Grid: (T/64, H, B). Block: 128 threads = 4 warps; each warp owns 16 q rows.
// K/V staged in 32-key tiles, cp.async double-buffered. S and PV via mma.
// q/k/v are tf32-clean (written rounded); Q scaled by 1/8 (exact).
// ---------------------------------------------------------------------------
__global__ void __launch_bounds__(128) attn_kernel()
{
    __shared__ float Ks[2][32][68];
    __shared__ float Vs[2][32][68];
    __shared__ float Ps[64][36];

    const float* q = g_scratch + OFF_Q;
    const float* k = g_scratch + OFF_K;
    const float* v = g_scratch + OFF_V;
    float* ctx     = g_scratch + OFF_CTX;

    const int qt   = blockIdx.x;
    const int head = blockIdx.y;
    const int b    = blockIdx.z;
    const int tid  = threadIdx.x;
    const int w    = tid >> 5;
    const int lane = tid & 31;
    const int g    = lane >> 2;
    const int t    = lane & 3;

    const int q0 = qt * 64;
    const size_t headoff = (size_t)head * 64;
    const size_t rowbase = (size_t)b * TT;

    auto issueKV = [&](int kt2, int bf) {
        const size_t kbase = (rowbase + (size_t)kt2 * 32) * DD + headoff;
        #pragma unroll
        for (int j = 0; j < 4; j++) {
            const int idx = tid + j * 128;     // 0..511
            const int row = idx >> 4;          // 0..31
            const int e4  = (idx & 15) << 2;
            cpa16(&Ks[bf][row][e4], k + kbase + (size_t)row * DD + e4);
            cpa16(&Vs[bf][row][e4], v + kbase + (size_t)row * DD + e4);
        }
        cpa_commit();
    };

    issueKV(0, 0);

    // Stage Q through Ps in two 32-col halves; build fragments (x 1/8 exact)
    unsigned Qf[8][4];
    #pragma unroll
    for (int h2 = 0; h2 < 2; h2++) {
        __syncthreads();
        #pragma unroll
        for (int j = 0; j < 4; j++) {
            const int idx = tid + j * 128;     // 0..511
            const int row = idx >> 3;          // 0..63
            const int e4  = (idx & 7) << 2;
            cpa16(&Ps[row][e4], q + (rowbase + q0 + row) * DD + headoff + h2 * 32 + e4);
        }
        cpa_commit();
        cpa_wait0();
        __syncthreads();
        #pragma unroll
        for (int ks = 0; ks < 4; ks++) {
            const int kk = h2 * 4 + ks;
            Qf[kk][0] = __float_as_uint(Ps[16*w + g    ][ks*8 + t    ] * 0.125f);
            Qf[kk][1] = __float_as_uint(Ps[16*w + g + 8][ks*8 + t    ] * 0.125f);
            Qf[kk][2] = __float_as_uint(Ps[16*w + g    ][ks*8 + t + 4] * 0.125f);
            Qf[kk][3] = __float_as_uint(Ps[16*w + g + 8][ks*8 + t + 4] * 0.125f);
        }
    }
    __syncthreads();
    issueKV(0, 0);   // re-issue tile 0 (Q staging waits drained all groups)

    float Oacc[8][4];
    #pragma unroll
    for (int nt = 0; nt < 8; nt++)
        #pragma unroll
        for (int r = 0; r < 4; r++) Oacc[nt][r] = 0.f;
    float m0 = -1e30f, m1 = -1e30f, l0 = 0.f, l1 = 0.f;

    const int nkt = (qt + 1) * 2;

    for (int kt = 0; kt < nkt; kt++) {
        const int buf = kt & 1;
        cpa_wait0();
        __syncthreads();
        if (kt + 1 < nkt) issueKV(kt + 1, buf ^ 1);

        // ---- S = Q K^T (64 x 32) ----
        float S[4][4];
        #pragma unroll
        for (int nt = 0; nt < 4; nt++)
            #pragma unroll
            for (int r = 0; r < 4; r++) S[nt][r] = 0.f;

        #pragma unroll
        for (int ks = 0; ks < 8; ks++) {
            unsigned bfrag[4][2];
            #pragma unroll
            for (int nt = 0; nt < 4; nt++) {
                bfrag[nt][0] = __float_as_uint(Ks[buf][nt*8 + g][ks*8 + t    ]);
                bfrag[nt][1] = __float_as_uint(Ks[buf][nt*8 + g][ks*8 + t + 4]);
            }
            #pragma unroll
            for (int nt = 0; nt < 4; nt++)
                mma_tf32(S[nt], Qf[ks], bfrag[nt]);
        }

        // ---- mask + online softmax ----
        const int ktbase = kt * 32;
        const int qrow0 = q0 + 16*w + g;
        const int qrow1 = qrow0 + 8;
        if (kt >= 2 * qt) {
            #pragma unroll
            for (int nt = 0; nt < 4; nt++) {
                const int key = ktbase + nt*8 + 2*t;
                if (key     > qrow0) S[nt][0] = -1e30f;
                if (key + 1 > qrow0) S[nt][1] = -1e30f;
                if (key     > qrow1) S[nt][2] = -1e30f;
                if (key + 1 > qrow1) S[nt][3] = -1e30f;
            }
        }
        float mn0 = m0, mn1 = m1;
        #pragma unroll
        for (int nt = 0; nt < 4; nt++) {
            mn0 = fmaxf(mn0, fmaxf(S[nt][0], S[nt][1]));
            mn1 = fmaxf(mn1, fmaxf(S[nt][2], S[nt][3]));
        }
        mn0 = fmaxf(mn0, __shfl_xor_sync(0xffffffffu, mn0, 1));
        mn0 = fmaxf(mn0, __shfl_xor_sync(0xffffffffu, mn0, 2));
        mn1 = fmaxf(mn1, __shfl_xor_sync(0xffffffffu, mn1, 1));
        mn1 = fmaxf(mn1, __shfl_xor_sync(0xffffffffu, mn1, 2));

        const float corr0 = __expf(m0 - mn0);
        const float corr1 = __expf(m1 - mn1);
        m0 = mn0; m1 = mn1;

        float ls0 = 0.f, ls1 = 0.f;
        #pragma unroll
        for (int nt = 0; nt < 4; nt++) {
            float p00 = tfr(__expf(S[nt][0] - m0));
            float p01 = tfr(__expf(S[nt][1] - m0));
            float p10 = tfr(__expf(S[nt][2] - m1));
            float p11 = tfr(__expf(S[nt][3] - m1));
            ls0 += p00 + p01;
            ls1 += p10 + p11;
            *(float2*)&Ps[16*w + g    ][nt*8 + 2*t] = make_float2(p00, p01);
            *(float2*)&Ps[16*w + g + 8][nt*8 + 2*t] = make_float2(p10, p11);
        }
        ls0 += __shfl_xor_sync(0xffffffffu, ls0, 1);
        ls0 += __shfl_xor_sync(0xffffffffu, ls0, 2);
        ls1 += __shfl_xor_sync(0xffffffffu, ls1, 1);
        ls1 += __shfl_xor_sync(0xffffffffu, ls1, 2);
        l0 = l0 * corr0 + ls0;
        l1 = l1 * corr1 + ls1;

        #pragma unroll
        for (int nt = 0; nt < 8; nt++) {
            Oacc[nt][0] *= corr0; Oacc[nt][1] *= corr0;
            Oacc[nt][2] *= corr1; Oacc[nt][3] *= corr1;
        }

        __syncwarp();

        // ---- O += P V (64 x 64, k=32) ----
        #pragma unroll
        for (int ks = 0; ks < 4; ks++) {
            unsigned af[4];
            af[0] = __float_as_uint(Ps[16*w + g    ][ks*8 + t    ]);
            af[1] = __float_as_uint(Ps[16*w + g + 8][ks*8 + t    ]);
            af[2] = __float_as_uint(Ps[16*w + g    ][ks*8 + t + 4]);
            af[3] = __float_as_uint(Ps[16*w + g + 8][ks*8 + t + 4]);
            #pragma unroll
            for (int nt = 0; nt < 8; nt++) {
                unsigned bfrag[2];
                bfrag[0] = __float_as_uint(Vs[buf][ks*8 + t    ][nt*8 + g]);
                bfrag[1] = __float_as_uint(Vs[buf][ks*8 + t + 4][nt*8 + g]);
                mma_tf32(Oacc[nt], af, bfrag);
            }
        }
        __syncwarp();   // protect Ps before next iteration's softmax writes
    }

    // ---- epilogue: normalize + store (rounded: ctx feeds Wo GEMM) ----
    const float inv0 = 1.f / l0;
    const float inv1 = 1.f / l1;
    float* base0 = ctx + (rowbase + q0 + 16*w + g    ) * DD + headoff;
    float* base1 = ctx + (rowbase + q0 + 16*w + g + 8) * DD + headoff;
    #pragma unroll
    for (int nt = 0; nt < 8; nt++) {
        const int col = nt*8 + 2*t;
        *(float2*)(base0 + col) = make_float2(tfr(Oacc[nt][0] * inv0), tfr(Oacc[nt][1] * inv0));
        *(float2*)(base1 + col) = make_float2(tfr(Oacc[nt][2] * inv1), tfr(Oacc[nt][3] * inv1));
    }
}

// ---------------------------------------------------------------------------
// Launch
// ---------------------------------------------------------------------------
extern "C" void kernel_launch(void* const* d_in, const int* in_sizes, int n_in,
                              void* d_out, int out_size)
{
    const float* x   = (const float*)d_in[0];
    const float* Wq  = (const float*)d_in[1];
    const float* Wk  = (const float*)d_in[2];
    const float* Wv  = (const float*)d_in[3];
    const float* Wo  = (const float*)d_in[4];
    const float* bo  = (const float*)d_in[5];
    const float* W1  = (const float*)d_in[6];
    const float* b1  = (const float*)d_in[7];
    const float* W2  = (const float*)d_in[8];
    const float* b2  = (const float*)d_in[9];
    const float* g1  = (const float*)d_in[10];
    const float* be1 = (const float*)d_in[11];
    const float* g2  = (const float*)d_in[12];
    const float* be2 = (const float*)d_in[13];
    float* out = (float*)d_out;

    // 0) Weight conversion (tf32-clean copies in scratch)
    wconv_kernel<<<12288, 256>>>((const float4*)Wq, (const float4*)Wk, (const float4*)Wv,
                                 (const float4*)Wo, (const float4*)W1, (const float4*)W2);

    // 1) LN1: x -> h (rounded)
    ln_kernel<<<NROWS, 256>>>(x, 0, g1, be1, OFF_H);

    // 2) QKV projections (rounded outputs)
    dim3 gq(DD / 128, NROWS / 128);
    tgemm_kernel<1, false, false, false, true><<<gq, 256>>>(OFF_H, OFF_WQC, nullptr, nullptr, 0, nullptr, OFF_Q, NROWS, DD, DD);
    tgemm_kernel<1, false, false, false, true><<<gq, 256>>>(OFF_H, OFF_WKC, nullptr, nullptr, 0, nullptr, OFF_K, NROWS, DD, DD);
    tgemm_kernel<1, false, false, false, true><<<gq, 256>>>(OFF_H, OFF_WVC, nullptr, nullptr, 0, nullptr, OFF_V, NROWS, DD, DD);

    // 3) Tensor-core causal flash attention -> ctx (rounded)
    attn_kernel<<<dim3(TT / 64, HH, BB), 128>>>();

    // 4) Output projection + bias + residual(x): ctx -> x2 (NOT rounded)
    tgemm_kernel<0, true, false, true, false><<<gq, 256>>>(OFF_CTX, OFF_WOC, bo, x, 0, nullptr, OFF_X2, NROWS, DD, DD);

    // 5) LN2: x2 -> h (rounded)
    ln_kernel<<<NROWS, 256>>>(nullptr, OFF_X2, g2, be2, OFF_H);

    // 6) FFN1 (+bias, relu): h -> ff (rounded)
    dim3 gf1(DFF / 128, NROWS / 128);
    tgemm_kernel<0, true, true, false, true><<<gf1, 256>>>(OFF_H, OFF_W1C, b1, nullptr, 0, nullptr, OFF_FF, NROWS, DFF, DD);

    // 7) FFN2 (+bias, +residual x2) -> final output (NOT rounded)
    tgemm_kernel<0, true, false, true, false><<<gq, 256>>>(OFF_FF, OFF_W2C, b2, nullptr, OFF_X2, out, 0, NROWS, DD, DFF);
}

// round 7
// speedup vs baseline: 5.9874x; 1.8180x over previous
#include <cuda_runtime.h>
#include <cuda_fp16.h>
#include <cstdint>

// Problem constants
#define BB 4
#define TT 2048
#define DD 1024
#define HH 16
#define HD 64
#define DFF 4096
#define NROWS (BB * TT)          // 8192
#define EPS 1e-5f

// ---------------------------------------------------------------------------
// Scratch arena (sized in floats; half buffers alias float slots)
// ---------------------------------------------------------------------------
#define SEG ((size_t)NROWS * DD)
#define MW  ((size_t)1024 * 1024)
#define OFF_H   ((size_t)0)
#define OFF_Q   (SEG * 1)
#define OFF_K   (SEG * 2)
#define OFF_V   (SEG * 3)
#define OFF_CTX (SEG * 4)
#define OFF_X2  (SEG * 5)
#define OFF_FF  (SEG * 6)
#define OFF_WC  (SEG * 6 + (size_t)NROWS * DFF)
#define OFF_WQC (OFF_WC + MW * 0)
#define OFF_WKC (OFF_WC + MW * 1)
#define OFF_WVC (OFF_WC + MW * 2)
#define OFF_WOC (OFF_WC + MW * 3)
#define OFF_W1C (OFF_WC + MW * 4)
#define OFF_W2C (OFF_WC + MW * 8)
#define SCRATCH_FLOATS (OFF_WC + MW * 12)

__device__ __align__(256) float g_scratch[SCRATCH_FLOATS];

__device__ __forceinline__ const float* rsrc(const float* p, size_t off) {
    return p ? p : (const float*)(g_scratch + off);
}

__device__ __forceinline__ void cpa16(void* s, const void* g) {
    unsigned sp = (unsigned)__cvta_generic_to_shared(s);
    asm volatile("cp.async.cg.shared.global [%0], [%1], 16;\n" :: "r"(sp), "l"(g));
}
__device__ __forceinline__ void cpa_commit() { asm volatile("cp.async.commit_group;\n"); }
__device__ __forceinline__ void cpa_wait0()  { asm volatile("cp.async.wait_group 0;\n"); }
__device__ __forceinline__ void cpa_wait1()  { asm volatile("cp.async.wait_group 1;\n"); }

__device__ __forceinline__ void mma_f16(float* c, const unsigned* a, const unsigned* b) {
    asm volatile(
        "mma.sync.aligned.m16n8k16.row.col.f32.f16.f16.f32 "
        "{%0,%1,%2,%3}, {%4,%5,%6,%7}, {%8,%9}, {%0,%1,%2,%3};\n"
        : "+f"(c[0]), "+f"(c[1]), "+f"(c[2]), "+f"(c[3])
        : "r"(a[0]), "r"(a[1]), "r"(a[2]), "r"(a[3]), "r"(b[0]), "r"(b[1]));
}
__device__ __forceinline__ void ldsm_x4_trans(unsigned& r0, unsigned& r1,
                                              unsigned& r2, unsigned& r3,
                                              const void* p) {
    unsigned addr = (unsigned)__cvta_generic_to_shared(p);
    asm volatile("ldmatrix.sync.aligned.m8n8.x4.trans.shared.b16 {%0,%1,%2,%3}, [%4];"
                 : "=r"(r0), "=r"(r1), "=r"(r2), "=r"(r3) : "r"(addr));
}
__device__ __forceinline__ unsigned h2u(__half2 h) { return *(unsigned*)&h; }

// ---------------------------------------------------------------------------
// Weight transposes -> K-major [N][K] fp16 copies in scratch
// ---------------------------------------------------------------------------
__global__ void __launch_bounds__(256) trans_kernel(
    const float* __restrict__ in, size_t ooff, int K, int N)
{
    __shared__ float tile[32][33];
    __half* out = (__half*)(g_scratch + ooff);
    const int k0 = blockIdx.y * 32, n0 = blockIdx.x * 32;
    const int tx = threadIdx.x, ty = threadIdx.y;
    #pragma unroll
    for (int i = 0; i < 32; i += 8)
        tile[ty + i][tx] = in[(size_t)(k0 + ty + i) * N + n0 + tx];
    __syncthreads();
    #pragma unroll
    for (int i = 0; i < 32; i += 8)
        out[(size_t)(n0 + ty + i) * K + k0 + tx] = __float2half_rn(tile[tx][ty + i]);
}

// QKV: in[H][1024][64] -> out[(h*64+e)][1024] fp16
__global__ void __launch_bounds__(256) trans_qkv_kernel(
    const float* __restrict__ in, size_t ooff)
{
    __shared__ float tile[32][33];
    __half* out = (__half*)(g_scratch + ooff);
    const int head = blockIdx.z;
    const float* src = in + (size_t)head * 1024 * 64;
    const int k0 = blockIdx.y * 32, e0 = blockIdx.x * 32;
    const int tx = threadIdx.x, ty = threadIdx.y;
    #pragma unroll
    for (int i = 0; i < 32; i += 8)
        tile[ty + i][tx] = src[(size_t)(k0 + ty + i) * 64 + e0 + tx];
    __syncthreads();
    #pragma unroll
    for (int i = 0; i < 32; i += 8)
        out[(size_t)(head * 64 + e0 + ty + i) * 1024 + k0 + tx] = __float2half_rn(tile[tx][ty + i]);
}

// ---------------------------------------------------------------------------
// LayerNorm: fp32 in -> fp16 out
// ---------------------------------------------------------------------------
__global__ void __launch_bounds__(256) ln_kernel(
    const float* __restrict__ xext, size_t xoff,
    const float* __restrict__ g, const float* __restrict__ be, size_t ooff)
{
    const float* x = rsrc(xext, xoff);
    __half* out = (__half*)(g_scratch + ooff);

    const int row = blockIdx.x;
    const int t   = threadIdx.x;
    const float4* xr = (const float4*)(x + (size_t)row * DD);
    float4 v = xr[t];

    float s = v.x + v.y + v.z + v.w;
    float q = v.x*v.x + v.y*v.y + v.z*v.z + v.w*v.w;
    #pragma unroll
    for (int o = 16; o; o >>= 1) {
        s += __shfl_xor_sync(0xffffffffu, s, o);
        q += __shfl_xor_sync(0xffffffffu, q, o);
    }
    __shared__ float ss[8], sq[8];
    if ((t & 31) == 0) { ss[t >> 5] = s; sq[t >> 5] = q; }
    __syncthreads();
    s = 0.f; q = 0.f;
    #pragma unroll
    for (int i = 0; i < 8; i++) { s += ss[i]; q += sq[i]; }

    const float mean = s * (1.0f / DD);
    const float var  = q * (1.0f / DD) - mean * mean;
    const float r    = rsqrtf(var + EPS);

    float4 gv = ((const float4*)g)[t];
    float4 bv = ((const float4*)be)[t];
    __half2 h0 = __floats2half2_rn((v.x - mean) * r * gv.x + bv.x,
                                   (v.y - mean) * r * gv.y + bv.y);
    __half2 h1 = __floats2half2_rn((v.z - mean) * r * gv.z + bv.z,
                                   (v.w - mean) * r * gv.w + bv.w);
    uint2 o; o.x = h2u(h0); o.y = h2u(h1);
    *(uint2*)(out + (size_t)row * DD + t * 4) = o;
}

// ---------------------------------------------------------------------------
// FP16 tensor-core GEMM: C[M,N] = A[M,K] @ BT[N,K]^T (+bias, +resid, relu)
// 128x128x32 tiles, 256 threads = 8 warps (2x4), warp 64x32, m16n8k16.
// A, BT fp16 in scratch. OUTH: write fp16 to scratch, else fp32 (+resid fp32).
// ---------------------------------------------------------------------------
template<bool BIAS, bool RELU, bool RESID, bool OUTH>
__global__ void __launch_bounds__(256) hgemm_kernel(
    size_t aoff, size_t boff,
    const float* __restrict__ bias,
    const float* __restrict__ resid_ext, size_t resid_off,
    float* __restrict__ Cext, size_t coff,
    int M, int N, int K)
{
    const __half* A  = (const __half*)(g_scratch + aoff);
    const __half* Bt = (const __half*)(g_scratch + boff);
    const float* R = RESID ? rsrc(resid_ext, resid_off) : (const float*)nullptr;

    __shared__ __half As[2][128][40];
    __shared__ __half Bs[2][128][40];

    const int tid  = threadIdx.x;
    const int wid  = tid >> 5;
    const int lane = tid & 31;
    const int m0 = blockIdx.y * 128;
    const int n0 = blockIdx.x * 128;
    const int warp_m = (wid >> 2) * 64;
    const int warp_n = (wid & 3) * 32;
    const int g = lane >> 2;
    const int t = lane & 3;

    float acc[4][4][4];
    #pragma unroll
    for (int mt = 0; mt < 4; mt++)
        #pragma unroll
        for (int nt = 0; nt < 4; nt++)
            #pragma unroll
            for (int r = 0; r < 4; r++) acc[mt][nt][r] = 0.f;

    const int nk = K >> 5;

    auto issue = [&](int kk, int buf) {
        #pragma unroll
        for (int i = 0; i < 2; i++) {
            const int idx = tid + i * 256;
            const int r = idx >> 2;
            const int c = (idx & 3) << 3;
            cpa16(&As[buf][r][c], A  + (size_t)(m0 + r) * K + kk * 32 + c);
            cpa16(&Bs[buf][r][c], Bt + (size_t)(n0 + r) * K + kk * 32 + c);
        }
        cpa_commit();
    };

    issue(0, 0);

    for (int kk = 0; kk < nk; kk++) {
        const int buf = kk & 1;
        if (kk + 1 < nk) { issue(kk + 1, buf ^ 1); cpa_wait1(); }
        else             { cpa_wait0(); }
        __syncthreads();

        #pragma unroll
        for (int ks = 0; ks < 2; ks++) {
            unsigned af[4][4], bf[4][2];
            #pragma unroll
            for (int mt = 0; mt < 4; mt++) {
                const int r = warp_m + mt * 16;
                af[mt][0] = *(const unsigned*)&As[buf][r + g    ][ks*16 + 2*t    ];
                af[mt][1] = *(const unsigned*)&As[buf][r + g + 8][ks*16 + 2*t    ];
                af[mt][2] = *(const unsigned*)&As[buf][r + g    ][ks*16 + 2*t + 8];
                af[mt][3] = *(const unsigned*)&As[buf][r + g + 8][ks*16 + 2*t + 8];
            }
            #pragma unroll
            for (int nt = 0; nt < 4; nt++) {
                const int c = warp_n + nt * 8;
                bf[nt][0] = *(const unsigned*)&Bs[buf][c + g][ks*16 + 2*t    ];
                bf[nt][1] = *(const unsigned*)&Bs[buf][c + g][ks*16 + 2*t + 8];
            }
            #pragma unroll
            for (int mt = 0; mt < 4; mt++)
                #pragma unroll
                for (int nt = 0; nt < 4; nt++)
                    mma_f16(acc[mt][nt], af[mt], bf[nt]);
        }
        __syncthreads();
    }

    // Epilogue: c0 @(g, 2t), c1 @(g, 2t+1), c2 @(g+8, 2t), c3 @(g+8, 2t+1)
    #pragma unroll
    for (int mt = 0; mt < 4; mt++) {
        #pragma unroll
        for (int half_ = 0; half_ < 2; half_++) {
            const int gr = m0 + warp_m + mt * 16 + g + half_ * 8;
            const float* Rrow = RESID ? (R + (size_t)gr * N) : (const float*)nullptr;
            #pragma unroll
            for (int nt = 0; nt < 4; nt++) {
                const int gc = n0 + warp_n + nt * 8 + 2 * t;
                float v0 = acc[mt][nt][half_ * 2 + 0];
                float v1 = acc[mt][nt][half_ * 2 + 1];
                if (BIAS)  { v0 += bias[gc]; v1 += bias[gc + 1]; }
                if (RESID) { v0 += Rrow[gc]; v1 += Rrow[gc + 1]; }
                if (RELU)  { v0 = fmaxf(v0, 0.f); v1 = fmaxf(v1, 0.f); }
                if (OUTH) {
                    __half* Crow = (__half*)(g_scratch + coff) + (size_t)gr * N;
                    *(__half2*)(Crow + gc) = __floats2half2_rn(v0, v1);
                } else {
                    float* Crow = (Cext ? Cext : (g_scratch + coff)) + (size_t)gr * N;
                    *(float2*)(Crow + gc) = make_float2(v0, v1);
                }
            }
        }
    }
}

// ---------------------------------------------------------------------------
// FP16 tensor-core causal flash attention.
// Grid: (T/64, H, B). Block: 128 threads = 4 warps; warp owns 16 q rows.
// K/V in 32-key double-buffered SMEM tiles. P stays in registers
// (S-fragment layout == PV A-fragment layout). V loaded via ldmatrix.trans.
// ---------------------------------------------------------------------------
__global__ void __launch_bounds__(128) attn_kernel()
{
    __shared__ __half Ks[2][32][72];
    __shared__ __half Vs[2][32][72];

    const __half* qh = (const __half*)(g_scratch + OFF_Q);
    const __half* kh = (const __half*)(g_scratch + OFF_K);
    const __half* vh = (const __half*)(g_scratch + OFF_V);
    __half* ctx      = (__half*)(g_scratch + OFF_CTX);

    const int qt   = blockIdx.x;
    const int head = blockIdx.y;
    const int b    = blockIdx.z;
    const int tid  = threadIdx.x;
    const int w    = tid >> 5;
    const int lane = tid & 31;
    const int g    = lane >> 2;
    const int t    = lane & 3;

    const int q0 = qt * 64;
    const size_t headoff = (size_t)head * 64;
    const size_t rowbase = (size_t)b * TT;

    auto issueKV = [&](int kt2, int bf) {
        const size_t kbase = (rowbase + (size_t)kt2 * 32) * DD + headoff;
        #pragma unroll
        for (int j = 0; j < 2; j++) {
            const int idx = tid + j * 128;     // 0..255
            const int row = idx >> 3;          // 0..31
            const int c   = (idx & 7) << 3;    // 0..56
            cpa16(&Ks[bf][row][c], kh + kbase + (size_t)row * DD + c);
            cpa16(&Vs[bf][row][c], vh + kbase + (size_t)row * DD + c);
        }
        cpa_commit();
    };

    issueKV(0, 0);

    // Q fragments straight from global (scaled by 1/8, exact in fp16)
    unsigned Qf[4][4];
    {
        const __half2 sc = __floats2half2_rn(0.125f, 0.125f);
        const size_t r0 = (rowbase + q0 + 16*w + g) * DD + headoff;
        const size_t r1 = r0 + 8 * DD;
        #pragma unroll
        for (int ks = 0; ks < 4; ks++) {
            const int e = ks * 16 + 2 * t;
            __half2 a0 = *(const __half2*)(qh + r0 + e);
            __half2 a1 = *(const __half2*)(qh + r1 + e);
            __half2 a2 = *(const __half2*)(qh + r0 + e + 8);
            __half2 a3 = *(const __half2*)(qh + r1 + e + 8);
            Qf[ks][0] = h2u(__hmul2(a0, sc));
            Qf[ks][1] = h2u(__hmul2(a1, sc));
            Qf[ks][2] = h2u(__hmul2(a2, sc));
            Qf[ks][3] = h2u(__hmul2(a3, sc));
        }
    }

    float Oacc[8][4];
    #pragma unroll
    for (int nt = 0; nt < 8; nt++)
        #pragma unroll
        for (int r = 0; r < 4; r++) Oacc[nt][r] = 0.f;
    float m0 = -1e30f, m1 = -1e30f, l0 = 0.f, l1 = 0.f;

    const int nkt = (qt + 1) * 2;

    for (int kt = 0; kt < nkt; kt++) {
        const int buf = kt & 1;
        cpa_wait0();
        __syncthreads();
        if (kt + 1 < nkt) issueKV(kt + 1, buf ^ 1);

        // ---- S = Q K^T (64 x 32) ----
        float S[4][4];
        #pragma unroll
        for (int nt = 0; nt < 4; nt++)
            #pragma unroll
            for (int r = 0; r < 4; r++) S[nt][r] = 0.f;

        #pragma unroll
        for (int ks = 0; ks < 4; ks++) {
            #pragma unroll
            for (int nt = 0; nt < 4; nt++) {
                unsigned bfrag[2];
                bfrag[0] = *(const unsigned*)&Ks[buf][nt*8 + g][ks*16 + 2*t    ];
                bfrag[1] = *(const unsigned*)&Ks[buf][nt*8 + g][ks*16 + 2*t + 8];
                mma_f16(S[nt], Qf[ks], bfrag);
            }
        }

        // ---- mask + online softmax ----
        const int qrow0 = q0 + 16*w + g;
        const int qrow1 = qrow0 + 8;
        if (kt >= 2 * qt) {
            const int ktbase = kt * 32;
            #pragma unroll
            for (int nt = 0; nt < 4; nt++) {
                const int key = ktbase + nt*8 + 2*t;
                if (key     > qrow0) S[nt][0] = -1e30f;
                if (key + 1 > qrow0) S[nt][1] = -1e30f;
                if (key     > qrow1) S[nt][2] = -1e30f;
                if (key + 1 > qrow1) S[nt][3] = -1e30f;
            }
        }
        float mn0 = m0, mn1 = m1;
        #pragma unroll
        for (int nt = 0; nt < 4; nt++) {
            mn0 = fmaxf(mn0, fmaxf(S[nt][0], S[nt][1]));
            mn1 = fmaxf(mn1, fmaxf(S[nt][2], S[nt][3]));
        }
        mn0 = fmaxf(mn0, __shfl_xor_sync(0xffffffffu, mn0, 1));
        mn0 = fmaxf(mn0, __shfl_xor_sync(0xffffffffu, mn0, 2));
        mn1 = fmaxf(mn1, __shfl_xor_sync(0xffffffffu, mn1, 1));
        mn1 = fmaxf(mn1, __shfl_xor_sync(0xffffffffu, mn1, 2));

        const float corr0 = __expf(m0 - mn0);
        const float corr1 = __expf(m1 - mn1);
        m0 = mn0; m1 = mn1;

        // P in registers: S fragment layout == PV A fragment layout
        unsigned Pa[4][2];
        float ls0 = 0.f, ls1 = 0.f;
        #pragma unroll
        for (int nt = 0; nt < 4; nt++) {
            __half2 p0 = __floats2half2_rn(__expf(S[nt][0] - m0), __expf(S[nt][1] - m0));
            __half2 p1 = __floats2half2_rn(__expf(S[nt][2] - m1), __expf(S[nt][3] - m1));
            Pa[nt][0] = h2u(p0);
            Pa[nt][1] = h2u(p1);
            const float2 f0 = __half22float2(p0);
            const float2 f1 = __half22float2(p1);
            ls0 += f0.x + f0.y;
            ls1 += f1.x + f1.y;
        }
        ls0 += __shfl_xor_sync(0xffffffffu, ls0, 1);
        ls0 += __shfl_xor_sync(0xffffffffu, ls0, 2);
        ls1 += __shfl_xor_sync(0xffffffffu, ls1, 1);
        ls1 += __shfl_xor_sync(0xffffffffu, ls1, 2);
        l0 = l0 * corr0 + ls0;
        l1 = l1 * corr1 + ls1;

        #pragma unroll
        for (int nt = 0; nt < 8; nt++) {
            Oacc[nt][0] *= corr0; Oacc[nt][1] *= corr0;
            Oacc[nt][2] *= corr1; Oacc[nt][3] *= corr1;
        }

        // ---- O += P V (64 x 64, k=32) ----
        #pragma unroll
        for (int ks = 0; ks < 2; ks++) {
            unsigned af[4];
            af[0] = Pa[2*ks    ][0];
            af[1] = Pa[2*ks    ][1];
            af[2] = Pa[2*ks + 1][0];
            af[3] = Pa[2*ks + 1][1];
            #pragma unroll
            for (int np = 0; np < 4; np++) {
                const int vrow = ks * 16 + (lane & 7) + ((lane >> 3) & 1) * 8;
                const int vcol = 8 * (2 * np + (lane >> 4));
                unsigned b0, b1, b2, b3;
                ldsm_x4_trans(b0, b1, b2, b3, &Vs[buf][vrow][vcol]);
                unsigned bf0[2] = {b0, b1};
                unsigned bf1[2] = {b2, b3};
                mma_f16(Oacc[2*np    ], af, bf0);
                mma_f16(Oacc[2*np + 1], af, bf1);
            }
        }
    }

    // ---- epilogue: normalize + store fp16 ctx ----
    const float inv0 = 1.f / l0;
    const float inv1 = 1.f / l1;
    __half* base0 = ctx + (rowbase + q0 + 16*w + g    ) * DD + headoff;
    __half* base1 = ctx + (rowbase + q0 + 16*w + g + 8) * DD + headoff;
    #pragma unroll
    for (int nt = 0; nt < 8; nt++) {
        const int col = nt*8 + 2*t;
        *(__half2*)(base0 + col) = __floats2half2_rn(Oacc[nt][0] * inv0, Oacc[nt][1] * inv0);
        *(__half2*)(base1 + col) = __floats2half2_rn(Oacc[nt][2] * inv1, Oacc[nt][3] * inv1);
    }
}

// ---------------------------------------------------------------------------
// Launch
// ---------------------------------------------------------------------------
extern "C" void kernel_launch(void* const* d_in, const int* in_sizes, int n_in,
                              void* d_out, int out_size)
{
    const float* x   = (const float*)d_in[0];
    const float* Wq  = (const float*)d_in[1];
    const float* Wk  = (const float*)d_in[2];
    const float* Wv  = (const float*)d_in[3];
    const float* Wo  = (const float*)d_in[4];
    const float* bo  = (const float*)d_in[5];
    const float* W1  = (const float*)d_in[6];
    const float* b1  = (const float*)d_in[7];
    const float* W2  = (const float*)d_in[8];
    const float* b2  = (const float*)d_in[9];
    const float* g1  = (const float*)d_in[10];
    const float* be1 = (const float*)d_in[11];
    const float* g2  = (const float*)d_in[12];
    const float* be2 = (const float*)d_in[13];
    float* out = (float*)d_out;

    // 0) Weight transposes -> K-major fp16 copies
    trans_qkv_kernel<<<dim3(2, 32, 16), dim3(32, 8)>>>(Wq, OFF_WQC);
    trans_qkv_kernel<<<dim3(2, 32, 16), dim3(32, 8)>>>(Wk, OFF_WKC);
    trans_qkv_kernel<<<dim3(2, 32, 16), dim3(32, 8)>>>(Wv, OFF_WVC);
    trans_kernel<<<dim3(32, 32),  dim3(32, 8)>>>(Wo, OFF_WOC, 1024, 1024);
    trans_kernel<<<dim3(128, 32), dim3(32, 8)>>>(W1, OFF_W1C, 1024, 4096);
    trans_kernel<<<dim3(32, 128), dim3(32, 8)>>>(W2, OFF_W2C, 4096, 1024);

    // 1) LN1: x -> h (fp16)
    ln_kernel<<<NROWS, 256>>>(x, 0, g1, be1, OFF_H);

    // 2) QKV projections (fp16 out)
    dim3 gq(DD / 128, NROWS / 128);
    hgemm_kernel<false,false,false,true><<<gq, 256>>>(OFF_H, OFF_WQC, nullptr, nullptr, 0, nullptr, OFF_Q, NROWS, DD, DD);
    hgemm_kernel<false,false,false,true><<<gq, 256>>>(OFF_H, OFF_WKC, nullptr, nullptr, 0, nullptr, OFF_K, NROWS, DD, DD);
    hgemm_kernel<false,false,false,true><<<gq, 256>>>(OFF_H, OFF_WVC, nullptr, nullptr, 0, nullptr, OFF_V, NROWS, DD, DD);

    // 3) FP16 tensor-core causal flash attention -> ctx (fp16)
    attn_kernel<<<dim3(TT / 64, HH, BB), 128>>>();

    // 4) Output projection + bias + residual(x): ctx -> x2 (fp32)
    hgemm_kernel<true,false,true,false><<<gq, 256>>>(OFF_CTX, OFF_WOC, bo, x, 0, nullptr, OFF_X2, NROWS, DD, DD);

    // 5) LN2: x2 -> h (fp16)
    ln_kernel<<<NROWS, 256>>>(nullptr, OFF_X2, g2, be2, OFF_H);

    // 6) FFN1 (+bias, relu): h -> ff (fp16)
    dim3 gf1(DFF / 128, NROWS / 128);
    hgemm_kernel<true,true,false,true><<<gf1, 256>>>(OFF_H, OFF_W1C, b1, nullptr, 0, nullptr, OFF_FF, NROWS, DFF, DD);

    // 7) FFN2 (+bias, +residual x2) -> final output (fp32)
    hgemm_kernel<true,false,true,false><<<gq, 256>>>(OFF_FF, OFF_W2C, b2, nullptr, OFF_X2, out, 0, NROWS, DD, DFF);
}

// round 8
// speedup vs baseline: 7.1613x; 1.1961x over previous
#include <cuda_runtime.h>
#include <cuda_fp16.h>
#include <cstdint>

// Problem constants
#define BB 4
#define TT 2048
#define DD 1024
#define HH 16
#define HD 64
#define DFF 4096
#define NROWS (BB * TT)          // 8192
#define EPS 1e-5f

// ---------------------------------------------------------------------------
// Scratch arena (sized in floats; half buffers alias float slots)
// ---------------------------------------------------------------------------
#define SEG ((size_t)NROWS * DD)
#define MW  ((size_t)1024 * 1024)
#define OFF_H   ((size_t)0)
#define OFF_Q   (SEG * 1)
#define OFF_K   (SEG * 2)
#define OFF_V   (SEG * 3)
#define OFF_CTX (SEG * 4)
#define OFF_X2  (SEG * 5)
#define OFF_FF  (SEG * 6)
#define OFF_WC  (SEG * 6 + (size_t)NROWS * DFF)
#define OFF_WQC (OFF_WC + MW * 0)
#define OFF_WKC (OFF_WC + MW * 1)
#define OFF_WVC (OFF_WC + MW * 2)
#define OFF_WOC (OFF_WC + MW * 3)
#define OFF_W1C (OFF_WC + MW * 4)
#define OFF_W2C (OFF_WC + MW * 8)
#define SCRATCH_FLOATS (OFF_WC + MW * 12)

__device__ __align__(256) float g_scratch[SCRATCH_FLOATS];

__device__ __forceinline__ const float* rsrc(const float* p, size_t off) {
    return p ? p : (const float*)(g_scratch + off);
}

__device__ __forceinline__ void cpa16(void* s, const void* g) {
    unsigned sp = (unsigned)__cvta_generic_to_shared(s);
    asm volatile("cp.async.cg.shared.global [%0], [%1], 16;\n" :: "r"(sp), "l"(g));
}
__device__ __forceinline__ void cpa_commit() { asm volatile("cp.async.commit_group;\n"); }
__device__ __forceinline__ void cpa_wait0()  { asm volatile("cp.async.wait_group 0;\n"); }
__device__ __forceinline__ void cpa_wait1()  { asm volatile("cp.async.wait_group 1;\n"); }

__device__ __forceinline__ void mma_f16(float* c, const unsigned* a, const unsigned* b) {
    asm volatile(
        "mma.sync.aligned.m16n8k16.row.col.f32.f16.f16.f32 "
        "{%0,%1,%2,%3}, {%4,%5,%6,%7}, {%8,%9}, {%0,%1,%2,%3};\n"
        : "+f"(c[0]), "+f"(c[1]), "+f"(c[2]), "+f"(c[3])
        : "r"(a[0]), "r"(a[1]), "r"(a[2]), "r"(a[3]), "r"(b[0]), "r"(b[1]));
}
__device__ __forceinline__ void ldsm_x4(unsigned& r0, unsigned& r1,
                                        unsigned& r2, unsigned& r3,
                                        const void* p) {
    unsigned addr = (unsigned)__cvta_generic_to_shared(p);
    asm volatile("ldmatrix.sync.aligned.m8n8.x4.shared.b16 {%0,%1,%2,%3}, [%4];"
                 : "=r"(r0), "=r"(r1), "=r"(r2), "=r"(r3) : "r"(addr));
}
__device__ __forceinline__ void ldsm_x4_trans(unsigned& r0, unsigned& r1,
                                              unsigned& r2, unsigned& r3,
                                              const void* p) {
    unsigned addr = (unsigned)__cvta_generic_to_shared(p);
    asm volatile("ldmatrix.sync.aligned.m8n8.x4.trans.shared.b16 {%0,%1,%2,%3}, [%4];"
                 : "=r"(r0), "=r"(r1), "=r"(r2), "=r"(r3) : "r"(addr));
}
__device__ __forceinline__ unsigned h2u(__half2 h) { return *(unsigned*)&h; }

// ---------------------------------------------------------------------------
// Weight transposes -> K-major [N][K] fp16 copies in scratch
// ---------------------------------------------------------------------------
__global__ void __launch_bounds__(256) trans_kernel(
    const float* __restrict__ in, size_t ooff, int K, int N)
{
    __shared__ float tile[32][33];
    __half* out = (__half*)(g_scratch + ooff);
    const int k0 = blockIdx.y * 32, n0 = blockIdx.x * 32;
    const int tx = threadIdx.x, ty = threadIdx.y;
    #pragma unroll
    for (int i = 0; i < 32; i += 8)
        tile[ty + i][tx] = in[(size_t)(k0 + ty + i) * N + n0 + tx];
    __syncthreads();
    #pragma unroll
    for (int i = 0; i < 32; i += 8)
        out[(size_t)(n0 + ty + i) * K + k0 + tx] = __float2half_rn(tile[tx][ty + i]);
}

// QKV: in[H][1024][64] -> out[(h*64+e)][1024] fp16
__global__ void __launch_bounds__(256) trans_qkv_kernel(
    const float* __restrict__ in, size_t ooff)
{
    __shared__ float tile[32][33];
    __half* out = (__half*)(g_scratch + ooff);
    const int head = blockIdx.z;
    const float* src = in + (size_t)head * 1024 * 64;
    const int k0 = blockIdx.y * 32, e0 = blockIdx.x * 32;
    const int tx = threadIdx.x, ty = threadIdx.y;
    #pragma unroll
    for (int i = 0; i < 32; i += 8)
        tile[ty + i][tx] = src[(size_t)(k0 + ty + i) * 64 + e0 + tx];
    __syncthreads();
    #pragma unroll
    for (int i = 0; i < 32; i += 8)
        out[(size_t)(head * 64 + e0 + ty + i) * 1024 + k0 + tx] = __float2half_rn(tile[tx][ty + i]);
}

// ---------------------------------------------------------------------------
// LayerNorm: fp32 in -> fp16 out
// ---------------------------------------------------------------------------
__global__ void __launch_bounds__(256) ln_kernel(
    const float* __restrict__ xext, size_t xoff,
    const float* __restrict__ g, const float* __restrict__ be, size_t ooff)
{
    const float* x = rsrc(xext, xoff);
    __half* out = (__half*)(g_scratch + ooff);

    const int row = blockIdx.x;
    const int t   = threadIdx.x;
    const float4* xr = (const float4*)(x + (size_t)row * DD);
    float4 v = xr[t];

    float s = v.x + v.y + v.z + v.w;
    float q = v.x*v.x + v.y*v.y + v.z*v.z + v.w*v.w;
    #pragma unroll
    for (int o = 16; o; o >>= 1) {
        s += __shfl_xor_sync(0xffffffffu, s, o);
        q += __shfl_xor_sync(0xffffffffu, q, o);
    }
    __shared__ float ss[8], sq[8];
    if ((t & 31) == 0) { ss[t >> 5] = s; sq[t >> 5] = q; }
    __syncthreads();
    s = 0.f; q = 0.f;
    #pragma unroll
    for (int i = 0; i < 8; i++) { s += ss[i]; q += sq[i]; }

    const float mean = s * (1.0f / DD);
    const float var  = q * (1.0f / DD) - mean * mean;
    const float r    = rsqrtf(var + EPS);

    float4 gv = ((const float4*)g)[t];
    float4 bv = ((const float4*)be)[t];
    __half2 h0 = __floats2half2_rn((v.x - mean) * r * gv.x + bv.x,
                                   (v.y - mean) * r * gv.y + bv.y);
    __half2 h1 = __floats2half2_rn((v.z - mean) * r * gv.z + bv.z,
                                   (v.w - mean) * r * gv.w + bv.w);
    uint2 o; o.x = h2u(h0); o.y = h2u(h1);
    *(uint2*)(out + (size_t)row * DD + t * 4) = o;
}

// ---------------------------------------------------------------------------
// FP16 tensor-core GEMM: C[M,N] = A[M,K] @ BT[N,K]^T (+bias, +resid, relu)
// 128x128x32 tiles, 256 threads = 8 warps (2x4), warp 64x32, m16n8k16.
// Fragment loads via ldmatrix.x4 (conflict-free with 40-half row stride).
// ---------------------------------------------------------------------------
template<bool BIAS, bool RELU, bool RESID, bool OUTH>
__global__ void __launch_bounds__(256) hgemm_kernel(
    size_t aoff, size_t boff,
    const float* __restrict__ bias,
    const float* __restrict__ resid_ext, size_t resid_off,
    float* __restrict__ Cext, size_t coff,
    int M, int N, int K)
{
    const __half* A  = (const __half*)(g_scratch + aoff);
    const __half* Bt = (const __half*)(g_scratch + boff);
    const float* R = RESID ? rsrc(resid_ext, resid_off) : (const float*)nullptr;

    __shared__ __half As[2][128][40];
    __shared__ __half Bs[2][128][40];

    const int tid  = threadIdx.x;
    const int wid  = tid >> 5;
    const int lane = tid & 31;
    const int m0 = blockIdx.y * 128;
    const int n0 = blockIdx.x * 128;
    const int warp_m = (wid >> 2) * 64;
    const int warp_n = (wid & 3) * 32;
    const int g = lane >> 2;
    const int t = lane & 3;

    // ldmatrix lane-address components
    const int lm_row = (lane & 7) + ((lane >> 3) & 1) * 8;  // row within 16-row block
    const int lm_col = (lane >> 4) * 8;                     // 0 or 8 (k-half)
    const int lb_row = ((lane >> 4) * 8) + (lane & 7);      // row within 16-n block
    const int lb_col = ((lane >> 3) & 1) * 8;               // 0 or 8 (k-half)

    float acc[4][4][4];
    #pragma unroll
    for (int mt = 0; mt < 4; mt++)
        #pragma unroll
        for (int nt = 0; nt < 4; nt++)
            #pragma unroll
            for (int r = 0; r < 4; r++) acc[mt][nt][r] = 0.f;

    const int nk = K >> 5;

    auto issue = [&](int kk, int buf) {
        #pragma unroll
        for (int i = 0; i < 2; i++) {
            const int idx = tid + i * 256;
            const int r = idx >> 2;
            const int c = (idx & 3) << 3;
            cpa16(&As[buf][r][c], A  + (size_t)(m0 + r) * K + kk * 32 + c);
            cpa16(&Bs[buf][r][c], Bt + (size_t)(n0 + r) * K + kk * 32 + c);
        }
        cpa_commit();
    };

    issue(0, 0);

    for (int kk = 0; kk < nk; kk++) {
        const int buf = kk & 1;
        if (kk + 1 < nk) { issue(kk + 1, buf ^ 1); cpa_wait1(); }
        else             { cpa_wait0(); }
        __syncthreads();

        #pragma unroll
        for (int ks = 0; ks < 2; ks++) {
            unsigned af[4][4], bf[4][2];
            #pragma unroll
            for (int mt = 0; mt < 4; mt++) {
                ldsm_x4(af[mt][0], af[mt][1], af[mt][2], af[mt][3],
                        &As[buf][warp_m + mt * 16 + lm_row][ks * 16 + lm_col]);
            }
            #pragma unroll
            for (int np = 0; np < 2; np++) {
                ldsm_x4(bf[2*np][0], bf[2*np][1], bf[2*np+1][0], bf[2*np+1][1],
                        &Bs[buf][warp_n + np * 16 + lb_row][ks * 16 + lb_col]);
            }
            #pragma unroll
            for (int mt = 0; mt < 4; mt++)
                #pragma unroll
                for (int nt = 0; nt < 4; nt++)
                    mma_f16(acc[mt][nt], af[mt], bf[nt]);
        }
        __syncthreads();
    }

    // Epilogue: c0 @(g, 2t), c1 @(g, 2t+1), c2 @(g+8, 2t), c3 @(g+8, 2t+1)
    #pragma unroll
    for (int mt = 0; mt < 4; mt++) {
        #pragma unroll
        for (int half_ = 0; half_ < 2; half_++) {
            const int gr = m0 + warp_m + mt * 16 + g + half_ * 8;
            const float* Rrow = RESID ? (R + (size_t)gr * N) : (const float*)nullptr;
            #pragma unroll
            for (int nt = 0; nt < 4; nt++) {
                const int gc = n0 + warp_n + nt * 8 + 2 * t;
                float v0 = acc[mt][nt][half_ * 2 + 0];
                float v1 = acc[mt][nt][half_ * 2 + 1];
                if (BIAS)  { v0 += bias[gc]; v1 += bias[gc + 1]; }
                if (RESID) { v0 += Rrow[gc]; v1 += Rrow[gc + 1]; }
                if (RELU)  { v0 = fmaxf(v0, 0.f); v1 = fmaxf(v1, 0.f); }
                if (OUTH) {
                    __half* Crow = (__half*)(g_scratch + coff) + (size_t)gr * N;
                    *(__half2*)(Crow + gc) = __floats2half2_rn(v0, v1);
                } else {
                    float* Crow = (Cext ? Cext : (g_scratch + coff)) + (size_t)gr * N;
                    *(float2*)(Crow + gc) = make_float2(v0, v1);
                }
            }
        }
    }
}

// ---------------------------------------------------------------------------
// FP16 tensor-core causal flash attention.
// Grid: (T/64, H, B). Block: 128 threads = 4 warps; warp owns 16 q rows.
// K fragments via ldmatrix.x4, V via ldmatrix.x4.trans, P in registers.
// ---------------------------------------------------------------------------
__global__ void __launch_bounds__(128) attn_kernel()
{
    __shared__ __half Ks[2][32][72];
    __shared__ __half Vs[2][32][72];

    const __half* qh = (const __half*)(g_scratch + OFF_Q);
    const __half* kh = (const __half*)(g_scratch + OFF_K);
    const __half* vh = (const __half*)(g_scratch + OFF_V);
    __half* ctx      = (__half*)(g_scratch + OFF_CTX);

    const int qt   = blockIdx.x;
    const int head = blockIdx.y;
    const int b    = blockIdx.z;
    const int tid  = threadIdx.x;
    const int w    = tid >> 5;
    const int lane = tid & 31;
    const int g    = lane >> 2;
    const int t    = lane & 3;

    const int lb_row = ((lane >> 4) * 8) + (lane & 7);
    const int lb_col = ((lane >> 3) & 1) * 8;

    const int q0 = qt * 64;
    const size_t headoff = (size_t)head * 64;
    const size_t rowbase = (size_t)b * TT;

    auto issueKV = [&](int kt2, int bf) {
        const size_t kbase = (rowbase + (size_t)kt2 * 32) * DD + headoff;
        #pragma unroll
        for (int j = 0; j < 2; j++) {
            const int idx = tid + j * 128;
            const int row = idx >> 3;
            const int c   = (idx & 7) << 3;
            cpa16(&Ks[bf][row][c], kh + kbase + (size_t)row * DD + c);
            cpa16(&Vs[bf][row][c], vh + kbase + (size_t)row * DD + c);
        }
        cpa_commit();
    };

    issueKV(0, 0);

    // Q fragments straight from global (scaled by 1/8, exact in fp16)
    unsigned Qf[4][4];
    {
        const __half2 sc = __floats2half2_rn(0.125f, 0.125f);
        const size_t r0 = (rowbase + q0 + 16*w + g) * DD + headoff;
        const size_t r1 = r0 + 8 * DD;
        #pragma unroll
        for (int ks = 0; ks < 4; ks++) {
            const int e = ks * 16 + 2 * t;
            __half2 a0 = *(const __half2*)(qh + r0 + e);
            __half2 a1 = *(const __half2*)(qh + r1 + e);
            __half2 a2 = *(const __half2*)(qh + r0 + e + 8);
            __half2 a3 = *(const __half2*)(qh + r1 + e + 8);
            Qf[ks][0] = h2u(__hmul2(a0, sc));
            Qf[ks][1] = h2u(__hmul2(a1, sc));
            Qf[ks][2] = h2u(__hmul2(a2, sc));
            Qf[ks][3] = h2u(__hmul2(a3, sc));
        }
    }

    float Oacc[8][4];
    #pragma unroll
    for (int nt = 0; nt < 8; nt++)
        #pragma unroll
        for (int r = 0; r < 4; r++) Oacc[nt][r] = 0.f;
    float m0 = -1e30f, m1 = -1e30f, l0 = 0.f, l1 = 0.f;

    const int nkt = (qt + 1) * 2;

    for (int kt = 0; kt < nkt; kt++) {
        const int buf = kt & 1;
        cpa_wait0();
        __syncthreads();
        if (kt + 1 < nkt) issueKV(kt + 1, buf ^ 1);

        // ---- S = Q K^T (64 x 32) ----
        float S[4][4];
        #pragma unroll
        for (int nt = 0; nt < 4; nt++)
            #pragma unroll
            for (int r = 0; r < 4; r++) S[nt][r] = 0.f;

        #pragma unroll
        for (int ks = 0; ks < 4; ks++) {
            unsigned bfrag[4][2];
            #pragma unroll
            for (int np = 0; np < 2; np++) {
                ldsm_x4(bfrag[2*np][0], bfrag[2*np][1], bfrag[2*np+1][0], bfrag[2*np+1][1],
                        &Ks[buf][np * 16 + lb_row][ks * 16 + lb_col]);
            }
            #pragma unroll
            for (int nt = 0; nt < 4; nt++)
                mma_f16(S[nt], Qf[ks], bfrag[nt]);
        }

        // ---- mask + online softmax ----
        const int qrow0 = q0 + 16*w + g;
        const int qrow1 = qrow0 + 8;
        if (kt >= 2 * qt) {
            const int ktbase = kt * 32;
            #pragma unroll
            for (int nt = 0; nt < 4; nt++) {
                const int key = ktbase + nt*8 + 2*t;
                if (key     > qrow0) S[nt][0] = -1e30f;
                if (key + 1 > qrow0) S[nt][1] = -1e30f;
                if (key     > qrow1) S[nt][2] = -1e30f;
                if (key + 1 > qrow1) S[nt][3] = -1e30f;
            }
        }
        float mn0 = m0, mn1 = m1;
        #pragma unroll
        for (int nt = 0; nt < 4; nt++) {
            mn0 = fmaxf(mn0, fmaxf(S[nt][0], S[nt][1]));
            mn1 = fmaxf(mn1, fmaxf(S[nt][2], S[nt][3]));
        }
        mn0 = fmaxf(mn0, __shfl_xor_sync(0xffffffffu, mn0, 1));
        mn0 = fmaxf(mn0, __shfl_xor_sync(0xffffffffu, mn0, 2));
        mn1 = fmaxf(mn1, __shfl_xor_sync(0xffffffffu, mn1, 1));
        mn1 = fmaxf(mn1, __shfl_xor_sync(0xffffffffu, mn1, 2));

        const float corr0 = __expf(m0 - mn0);
        const float corr1 = __expf(m1 - mn1);
        m0 = mn0; m1 = mn1;

        // P in registers: S fragment layout == PV A fragment layout
        unsigned Pa[4][2];
        float ls0 = 0.f, ls1 = 0.f;
        #pragma unroll
        for (int nt = 0; nt < 4; nt++) {
            __half2 p0 = __floats2half2_rn(__expf(S[nt][0] - m0), __expf(S[nt][1] - m0));
            __half2 p1 = __floats2half2_rn(__expf(S[nt][2] - m1), __expf(S[nt][3] - m1));
            Pa[nt][0] = h2u(p0);
            Pa[nt][1] = h2u(p1);
            const float2 f0 = __half22float2(p0);
            const float2 f1 = __half22float2(p1);
            ls0 += f0.x + f0.y;
            ls1 += f1.x + f1.y;
        }
        ls0 += __shfl_xor_sync(0xffffffffu, ls0, 1);
        ls0 += __shfl_xor_sync(0xffffffffu, ls0, 2);
        ls1 += __shfl_xor_sync(0xffffffffu, ls1, 1);
        ls1 += __shfl_xor_sync(0xffffffffu, ls1, 2);
        l0 = l0 * corr0 + ls0;
        l1 = l1 * corr1 + ls1;

        #pragma unroll
        for (int nt = 0; nt < 8; nt++) {
            Oacc[nt][0] *= corr0; Oacc[nt][1] *= corr0;
            Oacc[nt][2] *= corr1; Oacc[nt][3] *= corr1;
        }

        // ---- O += P V (64 x 64, k=32) ----
        #pragma unroll
        for (int ks = 0; ks < 2; ks++) {
            unsigned af[4];
            af[0] = Pa[2*ks    ][0];
            af[1] = Pa[2*ks    ][1];
            af[2] = Pa[2*ks + 1][0];
            af[3] = Pa[2*ks + 1][1];
            #pragma unroll
            for (int np = 0; np < 4; np++) {
                const int vrow = ks * 16 + (lane & 7) + ((lane >> 3) & 1) * 8;
                const int vcol = 8 * (2 * np + (lane >> 4));
                unsigned b0, b1, b2, b3;
                ldsm_x4_trans(b0, b1, b2, b3, &Vs[buf][vrow][vcol]);
                unsigned bf0[2] = {b0, b1};
                unsigned bf1[2] = {b2, b3};
                mma_f16(Oacc[2*np    ], af, bf0);
                mma_f16(Oacc[2*np + 1], af, bf1);
            }
        }
    }

    // ---- epilogue: normalize + store fp16 ctx ----
    const float inv0 = 1.f / l0;
    const float inv1 = 1.f / l1;
    __half* base0 = ctx + (rowbase + q0 + 16*w + g    ) * DD + headoff;
    __half* base1 = ctx + (rowbase + q0 + 16*w + g + 8) * DD + headoff;
    #pragma unroll
    for (int nt = 0; nt < 8; nt++) {
        const int col = nt*8 + 2*t;
        *(__half2*)(base0 + col) = __floats2half2_rn(Oacc[nt][0] * inv0, Oacc[nt][1] * inv0);
        *(__half2*)(base1 + col) = __floats2half2_rn(Oacc[nt][2] * inv1, Oacc[nt][3] * inv1);
    }
}

// ---------------------------------------------------------------------------
// Launch
// ---------------------------------------------------------------------------
extern "C" void kernel_launch(void* const* d_in, const int* in_sizes, int n_in,
                              void* d_out, int out_size)
{
    const float* x   = (const float*)d_in[0];
    const float* Wq  = (const float*)d_in[1];
    const float* Wk  = (const float*)d_in[2];
    const float* Wv  = (const float*)d_in[3];
    const float* Wo  = (const float*)d_in[4];
    const float* bo  = (const float*)d_in[5];
    const float* W1  = (const float*)d_in[6];
    const float* b1  = (const float*)d_in[7];
    const float* W2  = (const float*)d_in[8];
    const float* b2  = (const float*)d_in[9];
    const float* g1  = (const float*)d_in[10];
    const float* be1 = (const float*)d_in[11];
    const float* g2  = (const float*)d_in[12];
    const float* be2 = (const float*)d_in[13];
    float* out = (float*)d_out;

    // 0) Weight transposes -> K-major fp16 copies
    trans_qkv_kernel<<<dim3(2, 32, 16), dim3(32, 8)>>>(Wq, OFF_WQC);
    trans_qkv_kernel<<<dim3(2, 32, 16), dim3(32, 8)>>>(Wk, OFF_WKC);
    trans_qkv_kernel<<<dim3(2, 32, 16), dim3(32, 8)>>>(Wv, OFF_WVC);
    trans_kernel<<<dim3(32, 32),  dim3(32, 8)>>>(Wo, OFF_WOC, 1024, 1024);
    trans_kernel<<<dim3(128, 32), dim3(32, 8)>>>(W1, OFF_W1C, 1024, 4096);
    trans_kernel<<<dim3(32, 128), dim3(32, 8)>>>(W2, OFF_W2C, 4096, 1024);

    // 1) LN1: x -> h (fp16)
    ln_kernel<<<NROWS, 256>>>(x, 0, g1, be1, OFF_H);

    // 2) QKV projections (fp16 out)
    dim3 gq(DD / 128, NROWS / 128);
    hgemm_kernel<false,false,false,true><<<gq, 256>>>(OFF_H, OFF_WQC, nullptr, nullptr, 0, nullptr, OFF_Q, NROWS, DD, DD);
    hgemm_kernel<false,false,false,true><<<gq, 256>>>(OFF_H, OFF_WKC, nullptr, nullptr, 0, nullptr, OFF_K, NROWS, DD, DD);
    hgemm_kernel<false,false,false,true><<<gq, 256>>>(OFF_H, OFF_WVC, nullptr, nullptr, 0, nullptr, OFF_V, NROWS, DD, DD);

    // 3) FP16 tensor-core causal flash attention -> ctx (fp16)
    attn_kernel<<<dim3(TT / 64, HH, BB), 128>>>();

    // 4) Output projection + bias + residual(x): ctx -> x2 (fp32)
    hgemm_kernel<true,false,true,false><<<gq, 256>>>(OFF_CTX, OFF_WOC, bo, x, 0, nullptr, OFF_X2, NROWS, DD, DD);

    // 5) LN2: x2 -> h (fp16)
    ln_kernel<<<NROWS, 256>>>(nullptr, OFF_X2, g2, be2, OFF_H);

    // 6) FFN1 (+bias, relu): h -> ff (fp16)
    dim3 gf1(DFF / 128, NROWS / 128);
    hgemm_kernel<true,true,false,true><<<gf1, 256>>>(OFF_H, OFF_W1C, b1, nullptr, 0, nullptr, OFF_FF, NROWS, DFF, DD);

    // 7) FFN2 (+bias, +residual x2) -> final output (fp32)
    hgemm_kernel<true,false,true,false><<<gq, 256>>>(OFF_FF, OFF_W2C, b2, nullptr, OFF_X2, out, 0, NROWS, DD, DFF);
}